// round 1
// baseline (speedup 1.0000x reference)
#include <cuda_runtime.h>
#include <math.h>

// ---------------- problem constants ----------------
constexpr int kH     = 2048;
constexpr int kL     = 512;    // txt tokens
constexpr int kN     = 2048;   // img tokens
constexpr int kSEQ   = 2560;   // joint sequence
constexpr int kHEADS = 16;
constexpr int kHD    = 128;
constexpr int kMLP   = 8192;

// ---------------- scratch layout (single __device__ array, no allocs) ----
constexpr size_t OFF_SILU = 0;
constexpr size_t OFF_MOD  = OFF_SILU + kH;                       // 2 * 6*kH
constexpr size_t OFF_XN   = OFF_MOD  + (size_t)2 * 6 * kH;       // SEQ x H
constexpr size_t OFF_QKV  = OFF_XN   + (size_t)kSEQ * kH;        // SEQ x 3H
constexpr size_t OFF_Q    = OFF_QKV  + (size_t)kSEQ * 3 * kH;    // heads x SEQ x HD
constexpr size_t OFF_K    = OFF_Q    + (size_t)kHEADS * kSEQ * kHD;
constexpr size_t OFF_VT   = OFF_K    + (size_t)kHEADS * kSEQ * kHD;  // heads x HD x SEQ
constexpr size_t OFF_S    = OFF_VT   + (size_t)kHEADS * kHD * kSEQ;  // heads x SEQ x SEQ
constexpr size_t OFF_AO   = OFF_S    + (size_t)kHEADS * kSEQ * kSEQ; // SEQ x H
constexpr size_t OFF_RES  = OFF_AO   + (size_t)kSEQ * kH;            // SEQ x H
constexpr size_t OFF_H1   = OFF_RES  + (size_t)kSEQ * kH;            // N x MLP (reused)
constexpr size_t SCRATCH_TOTAL = OFF_H1 + (size_t)kN * kMLP;

__device__ float g_scratch[SCRATCH_TOTAL];

// ---------------- small helper kernels ----------------
__global__ void silu_kernel(const float* __restrict__ vec, float* __restrict__ out) {
    int i = blockIdx.x * blockDim.x + threadIdx.x;
    if (i < kH) {
        float v = vec[i];
        out[i] = v / (1.f + expf(-v));
    }
}

// e = silu(vec) @ W^T + b  for both txt and img adaLN weight sets.
// One warp per output element (24576 outputs total).
__global__ void adaln_gemv(const float* __restrict__ silu,
                           const float* __restrict__ tw, const float* __restrict__ tb,
                           const float* __restrict__ iw, const float* __restrict__ ib,
                           float* __restrict__ mod) {
    int gw = (blockIdx.x * blockDim.x + threadIdx.x) >> 5;
    int lane = threadIdx.x & 31;
    if (gw >= 2 * 6 * kH) return;
    int set = gw / (6 * kH);
    int o = gw - set * (6 * kH);
    const float* W = (set ? iw : tw) + (size_t)o * kH;
    float s = 0.f;
    for (int i = lane; i < kH; i += 32) s += silu[i] * W[i];
    #pragma unroll
    for (int off = 16; off; off >>= 1) s += __shfl_xor_sync(0xffffffffu, s, off);
    if (lane == 0) mod[(size_t)set * 6 * kH + o] = s + (set ? ib[o] : tb[o]);
}

// out = rms_norm(x, w) * (1 + sc) + sh, one block per row of 2048.
__global__ void norm_mod(const float* __restrict__ x, float* __restrict__ out,
                         const float* __restrict__ w,
                         const float* __restrict__ sh, const float* __restrict__ sc) {
    int row = blockIdx.x;
    const float* xr = x + (size_t)row * kH;
    float* orow = out + (size_t)row * kH;
    int tid = threadIdx.x;
    float ss = 0.f;
    for (int i = tid; i < kH; i += 256) { float v = xr[i]; ss += v * v; }
    __shared__ float sred[8];
    #pragma unroll
    for (int off = 16; off; off >>= 1) ss += __shfl_xor_sync(0xffffffffu, ss, off);
    if ((tid & 31) == 0) sred[tid >> 5] = ss;
    __syncthreads();
    if (tid < 8) {
        float v = sred[tid];
        #pragma unroll
        for (int off = 4; off; off >>= 1) v += __shfl_xor_sync(0xffu, v, off);
        if (tid == 0) sred[0] = v;
    }
    __syncthreads();
    float norm = rsqrtf(sred[0] * (1.f / kH) + 1e-6f);
    for (int i = tid; i < kH; i += 256)
        orow[i] = xr[i] * norm * w[i] * (1.f + sc[i]) + sh[i];
}

// Split qkv (SEQ x 6144), apply RoPE to img q/k, scatter to
// q,k: [head][seq][hd]  and v transposed: [head][hd][seq].
__global__ void rope_scatter(const float* __restrict__ qkv, const float* __restrict__ rope,
                             float* __restrict__ q, float* __restrict__ k,
                             float* __restrict__ vt) {
    int gid = blockIdx.x * blockDim.x + threadIdx.x;
    if (gid >= kSEQ * kHEADS * (kHD / 2)) return;
    int j = gid & 63;
    int h = (gid >> 6) & 15;
    int n = gid >> 10;
    int d = j * 2;
    const float* base = qkv + (size_t)n * 3 * kH;
    float q0 = base[h * kHD + d],          q1 = base[h * kHD + d + 1];
    float k0 = base[kH + h * kHD + d],     k1 = base[kH + h * kHD + d + 1];
    float v0 = base[2 * kH + h * kHD + d], v1 = base[2 * kH + h * kHD + d + 1];
    if (n >= kL) {
        const float* r = rope + (size_t)(n - kL) * kHD + d;
        float c = r[0], s = r[1];
        float t;
        t = q0 * c - q1 * s; q1 = q1 * c + q0 * s; q0 = t;
        t = k0 * c - k1 * s; k1 = k1 * c + k0 * s; k0 = t;
    }
    size_t qi = ((size_t)h * kSEQ + n) * kHD + d;
    q[qi] = q0; q[qi + 1] = q1;
    k[qi] = k0; k[qi + 1] = k1;
    size_t vi = ((size_t)h * kHD + d) * kSEQ + n;
    vt[vi] = v0; vt[vi + kSEQ] = v1;
}

// Row softmax over 2560 with scale, grid (SEQ, HEADS), 256 threads.
__global__ void softmax_rows(float* __restrict__ S) {
    float* p = S + ((size_t)blockIdx.y * kSEQ + blockIdx.x) * kSEQ;
    int tid = threadIdx.x;
    const float scale = 0.08838834764831845f;  // 128^-0.5
    float vals[10];
    float m = -3.4e38f;
    #pragma unroll
    for (int t = 0; t < 10; t++) { vals[t] = p[tid + t * 256] * scale; m = fmaxf(m, vals[t]); }
    __shared__ float sred[8];
    #pragma unroll
    for (int off = 16; off; off >>= 1) m = fmaxf(m, __shfl_xor_sync(0xffffffffu, m, off));
    if ((tid & 31) == 0) sred[tid >> 5] = m;
    __syncthreads();
    float m2 = sred[0];
    #pragma unroll
    for (int i = 1; i < 8; i++) m2 = fmaxf(m2, sred[i]);
    float sum = 0.f;
    #pragma unroll
    for (int t = 0; t < 10; t++) { vals[t] = __expf(vals[t] - m2); sum += vals[t]; }
    #pragma unroll
    for (int off = 16; off; off >>= 1) sum += __shfl_xor_sync(0xffffffffu, sum, off);
    __syncthreads();
    if ((tid & 31) == 0) sred[tid >> 5] = sum;
    __syncthreads();
    float tot = sred[0] + sred[1] + sred[2] + sred[3] + sred[4] + sred[5] + sred[6] + sred[7];
    float inv = 1.f / tot;
    #pragma unroll
    for (int t = 0; t < 10; t++) p[tid + t * 256] = vals[t] * inv;
}

// ---------------- generic NT SGEMM: C = A(MxK) * B(NxK)^T ----------------
// EPI 0: plain store
// EPI 1: bias + tanh-GELU
// EPI 2: C = res + gate[col] * (acc + optional bias[col])
constexpr int BM = 128, BN = 128, BK = 16;

__device__ __forceinline__ float gelu_tanh(float x) {
    float x3 = x * x * x;
    return 0.5f * x * (1.f + tanhf(0.7978845608028654f * (x + 0.044715f * x3)));
}

template <int EPI>
__global__ __launch_bounds__(256) void gemm_nt(
    const float* __restrict__ A, size_t sA,
    const float* __restrict__ B, size_t sB,
    float* __restrict__ C, size_t sC, int ldc,
    const float* __restrict__ bias,
    const float* __restrict__ gate,
    const float* __restrict__ res,
    int M, int N, int K)
{
    A += (size_t)blockIdx.z * sA;
    B += (size_t)blockIdx.z * sB;
    C += (size_t)blockIdx.z * sC;
    __shared__ __align__(16) float As[BK][BM + 4];
    __shared__ __align__(16) float Bs[BK][BN + 4];
    int tid = threadIdx.x;
    int tm = tid >> 4, tn = tid & 15;
    const float* Ag = A + (size_t)(blockIdx.y * BM) * K;
    const float* Bg = B + (size_t)(blockIdx.x * BN) * K;
    float acc[8][8];
    #pragma unroll
    for (int i = 0; i < 8; i++)
        #pragma unroll
        for (int j = 0; j < 8; j++) acc[i][j] = 0.f;

    for (int k0 = 0; k0 < K; k0 += BK) {
        #pragma unroll
        for (int ld = 0; ld < 2; ld++) {
            int idx = tid + ld * 256;
            int row = idx >> 2;
            int c4 = (idx & 3) * 4;
            float4 a = *(const float4*)(Ag + (size_t)row * K + k0 + c4);
            As[c4][row] = a.x; As[c4 + 1][row] = a.y; As[c4 + 2][row] = a.z; As[c4 + 3][row] = a.w;
            float4 b = *(const float4*)(Bg + (size_t)row * K + k0 + c4);
            Bs[c4][row] = b.x; Bs[c4 + 1][row] = b.y; Bs[c4 + 2][row] = b.z; Bs[c4 + 3][row] = b.w;
        }
        __syncthreads();
        #pragma unroll
        for (int k = 0; k < BK; k++) {
            float ar[8], br[8];
            *(float4*)(ar)     = *(const float4*)&As[k][tm * 8];
            *(float4*)(ar + 4) = *(const float4*)&As[k][tm * 8 + 4];
            *(float4*)(br)     = *(const float4*)&Bs[k][tn * 8];
            *(float4*)(br + 4) = *(const float4*)&Bs[k][tn * 8 + 4];
            #pragma unroll
            for (int i = 0; i < 8; i++)
                #pragma unroll
                for (int j = 0; j < 8; j++)
                    acc[i][j] = fmaf(ar[i], br[j], acc[i][j]);
        }
        __syncthreads();
    }

    int row0 = blockIdx.y * BM + tm * 8;
    int col0 = blockIdx.x * BN + tn * 8;
    #pragma unroll
    for (int i = 0; i < 8; i++) {
        #pragma unroll
        for (int j = 0; j < 8; j++) {
            float v = acc[i][j];
            int col = col0 + j;
            if (EPI == 1) {
                v += bias[col];
                v = gelu_tanh(v);
            } else if (EPI == 2) {
                if (bias) v += bias[col];
                v = res[(size_t)(row0 + i) * ldc + col] + gate[col] * v;
            }
            C[(size_t)(row0 + i) * ldc + col] = v;
        }
    }
}

// ---------------- launch ----------------
extern "C" void kernel_launch(void* const* d_in, const int* in_sizes, int n_in,
                              void* d_out, int out_size) {
    const float* txt           = (const float*)d_in[0];
    const float* img           = (const float*)d_in[1];
    const float* vec           = (const float*)d_in[2];
    const float* rope          = (const float*)d_in[3];
    const float* txt_adaln_w   = (const float*)d_in[4];
    const float* txt_adaln_b   = (const float*)d_in[5];
    const float* txt_adaln_rms = (const float*)d_in[6];
    const float* img_adaln_w   = (const float*)d_in[7];
    const float* img_adaln_b   = (const float*)d_in[8];
    const float* img_adaln_rms = (const float*)d_in[9];
    const float* txt_qkv_w     = (const float*)d_in[10];
    const float* img_qkv_w     = (const float*)d_in[11];
    const float* txt_out_w     = (const float*)d_in[12];
    const float* img_out_w     = (const float*)d_in[13];
    const float* txt_norm2_w   = (const float*)d_in[14];
    const float* img_norm2_w   = (const float*)d_in[15];
    const float* txt_fc1_w     = (const float*)d_in[16];
    const float* txt_fc1_b     = (const float*)d_in[17];
    const float* txt_fc2_w     = (const float*)d_in[18];
    const float* txt_fc2_b     = (const float*)d_in[19];
    const float* img_fc1_w     = (const float*)d_in[20];
    const float* img_fc1_b     = (const float*)d_in[21];
    const float* img_fc2_w     = (const float*)d_in[22];
    const float* img_fc2_b     = (const float*)d_in[23];
    float* out = (float*)d_out;
    (void)in_sizes; (void)n_in; (void)out_size;

    float* sc = nullptr;
    cudaGetSymbolAddress((void**)&sc, g_scratch);
    float* silu = sc + OFF_SILU;
    float* mod  = sc + OFF_MOD;
    float* tmod = mod;                 // [sh_msa, sc_msa, g_msa, sh_mlp, sc_mlp, g_mlp]
    float* imod = mod + 6 * kH;
    float* xn   = sc + OFF_XN;
    float* qkv  = sc + OFF_QKV;
    float* q    = sc + OFF_Q;
    float* k    = sc + OFF_K;
    float* vt   = sc + OFF_VT;
    float* S    = sc + OFF_S;
    float* ao   = sc + OFF_AO;
    float* res  = sc + OFF_RES;
    float* h1   = sc + OFF_H1;

    // adaLN modulation params
    silu_kernel<<<8, 256>>>(vec, silu);
    adaln_gemv<<<(2 * 6 * kH) / 8, 256>>>(silu, txt_adaln_w, txt_adaln_b,
                                          img_adaln_w, img_adaln_b, mod);

    // norm1 + modulation
    norm_mod<<<kL, 256>>>(txt, xn, txt_adaln_rms, tmod, tmod + kH);
    norm_mod<<<kN, 256>>>(img, xn + (size_t)kL * kH, img_adaln_rms, imod, imod + kH);

    // QKV projections
    gemm_nt<0><<<dim3(3 * kH / BN, kL / BM), 256>>>(
        xn, 0, txt_qkv_w, 0, qkv, 0, 3 * kH, nullptr, nullptr, nullptr, kL, 3 * kH, kH);
    gemm_nt<0><<<dim3(3 * kH / BN, kN / BM), 256>>>(
        xn + (size_t)kL * kH, 0, img_qkv_w, 0, qkv + (size_t)kL * 3 * kH, 0, 3 * kH,
        nullptr, nullptr, nullptr, kN, 3 * kH, kH);

    // RoPE + head scatter (V transposed)
    rope_scatter<<<(kSEQ * kHEADS * 64) / 256, 256>>>(qkv, rope, q, k, vt);

    // joint attention: S = Q K^T (per head), softmax, O = P V
    gemm_nt<0><<<dim3(kSEQ / BN, kSEQ / BM, kHEADS), 256>>>(
        q, (size_t)kSEQ * kHD, k, (size_t)kSEQ * kHD, S, (size_t)kSEQ * kSEQ, kSEQ,
        nullptr, nullptr, nullptr, kSEQ, kSEQ, kHD);
    softmax_rows<<<dim3(kSEQ, kHEADS), 256>>>(S);
    gemm_nt<0><<<dim3(kHD / BN, kSEQ / BM, kHEADS), 256>>>(
        S, (size_t)kSEQ * kSEQ, vt, (size_t)kHD * kSEQ, ao, (size_t)kHD, kH,
        nullptr, nullptr, nullptr, kSEQ, kHD, kSEQ);

    // output projections with gated residual
    gemm_nt<2><<<dim3(kH / BN, kL / BM), 256>>>(
        ao, 0, txt_out_w, 0, res, 0, kH, nullptr, tmod + 2 * kH, txt, kL, kH, kH);
    gemm_nt<2><<<dim3(kH / BN, kN / BM), 256>>>(
        ao + (size_t)kL * kH, 0, img_out_w, 0, res + (size_t)kL * kH, 0, kH,
        nullptr, imod + 2 * kH, img, kN, kH, kH);

    // norm2 + modulation
    norm_mod<<<kL, 256>>>(res, xn, txt_norm2_w, tmod + 3 * kH, tmod + 4 * kH);
    norm_mod<<<kN, 256>>>(res + (size_t)kL * kH, xn + (size_t)kL * kH,
                          img_norm2_w, imod + 3 * kH, imod + 4 * kH);

    // txt MLP (fc1 gelu, fc2 gated residual -> d_out)
    gemm_nt<1><<<dim3(kMLP / BN, kL / BM), 256>>>(
        xn, 0, txt_fc1_w, 0, h1, 0, kMLP, txt_fc1_b, nullptr, nullptr, kL, kMLP, kH);
    gemm_nt<2><<<dim3(kH / BN, kL / BM), 256>>>(
        h1, 0, txt_fc2_w, 0, out, 0, kH, txt_fc2_b, tmod + 5 * kH, res, kL, kH, kMLP);

    // img MLP (h1 reused after txt fc2 completes in-stream)
    gemm_nt<1><<<dim3(kMLP / BN, kN / BM), 256>>>(
        xn + (size_t)kL * kH, 0, img_fc1_w, 0, h1, 0, kMLP, img_fc1_b, nullptr, nullptr,
        kN, kMLP, kH);
    gemm_nt<2><<<dim3(kH / BN, kN / BM), 256>>>(
        h1, 0, img_fc2_w, 0, out + (size_t)kL * kH, 0, kH, img_fc2_b, imod + 5 * kH,
        res + (size_t)kL * kH, kN, kH, kMLP);
}

// round 2
// speedup vs baseline: 2.2385x; 2.2385x over previous
#include <cuda_runtime.h>
#include <math.h>
#include <stdint.h>

// ---------------- problem constants ----------------
constexpr int kH     = 2048;
constexpr int kL     = 512;    // txt tokens
constexpr int kN     = 2048;   // img tokens
constexpr int kSEQ   = 2560;   // joint sequence
constexpr int kHEADS = 16;
constexpr int kHD    = 128;
constexpr int kMLP   = 8192;

// ---------------- scratch layout (single __device__ array, no allocs) ----
constexpr size_t OFF_SILU = 0;
constexpr size_t OFF_MOD  = OFF_SILU + kH;                       // 2 * 6*kH
constexpr size_t OFF_XN   = OFF_MOD  + (size_t)2 * 6 * kH;       // SEQ x H
constexpr size_t OFF_QKV  = OFF_XN   + (size_t)kSEQ * kH;        // SEQ x 3H
constexpr size_t OFF_Q    = OFF_QKV  + (size_t)kSEQ * 3 * kH;    // heads x SEQ x HD
constexpr size_t OFF_K    = OFF_Q    + (size_t)kHEADS * kSEQ * kHD;
constexpr size_t OFF_VT   = OFF_K    + (size_t)kHEADS * kSEQ * kHD;  // heads x HD x SEQ
constexpr size_t OFF_S    = OFF_VT   + (size_t)kHEADS * kHD * kSEQ;  // heads x SEQ x SEQ
constexpr size_t OFF_AO   = OFF_S    + (size_t)kHEADS * kSEQ * kSEQ; // SEQ x H
constexpr size_t OFF_RES  = OFF_AO   + (size_t)kSEQ * kH;            // SEQ x H
constexpr size_t OFF_H1   = OFF_RES  + (size_t)kSEQ * kH;            // N x MLP (reused)
constexpr size_t SCRATCH_TOTAL = OFF_H1 + (size_t)kN * kMLP;

__device__ float g_scratch[SCRATCH_TOTAL];

// ---------------- small helper kernels ----------------
__global__ void silu_kernel(const float* __restrict__ vec, float* __restrict__ out) {
    int i = blockIdx.x * blockDim.x + threadIdx.x;
    if (i < kH) {
        float v = vec[i];
        out[i] = v / (1.f + expf(-v));
    }
}

__global__ void adaln_gemv(const float* __restrict__ silu,
                           const float* __restrict__ tw, const float* __restrict__ tb,
                           const float* __restrict__ iw, const float* __restrict__ ib,
                           float* __restrict__ mod) {
    int gw = (blockIdx.x * blockDim.x + threadIdx.x) >> 5;
    int lane = threadIdx.x & 31;
    if (gw >= 2 * 6 * kH) return;
    int set = gw / (6 * kH);
    int o = gw - set * (6 * kH);
    const float* W = (set ? iw : tw) + (size_t)o * kH;
    float s = 0.f;
    for (int i = lane; i < kH; i += 32) s += silu[i] * W[i];
    #pragma unroll
    for (int off = 16; off; off >>= 1) s += __shfl_xor_sync(0xffffffffu, s, off);
    if (lane == 0) mod[(size_t)set * 6 * kH + o] = s + (set ? ib[o] : tb[o]);
}

// out = rms_norm(x, w) * (1 + sc) + sh, one block per row of 2048.
__global__ void norm_mod(const float* __restrict__ x, float* __restrict__ out,
                         const float* __restrict__ w,
                         const float* __restrict__ sh, const float* __restrict__ sc) {
    int row = blockIdx.x;
    const float* xr = x + (size_t)row * kH;
    float* orow = out + (size_t)row * kH;
    int tid = threadIdx.x;
    float ss = 0.f;
    for (int i = tid; i < kH; i += 256) { float v = xr[i]; ss += v * v; }
    __shared__ float sred[8];
    #pragma unroll
    for (int off = 16; off; off >>= 1) ss += __shfl_xor_sync(0xffffffffu, ss, off);
    if ((tid & 31) == 0) sred[tid >> 5] = ss;
    __syncthreads();
    if (tid < 8) {
        float v = sred[tid];
        #pragma unroll
        for (int off = 4; off; off >>= 1) v += __shfl_xor_sync(0xffu, v, off);
        if (tid == 0) sred[0] = v;
    }
    __syncthreads();
    float norm = rsqrtf(sred[0] * (1.f / kH) + 1e-6f);
    for (int i = tid; i < kH; i += 256)
        orow[i] = xr[i] * norm * w[i] * (1.f + sc[i]) + sh[i];
}

// Split qkv, apply RoPE to img q/k, scatter heads; v stored transposed.
__global__ void rope_scatter(const float* __restrict__ qkv, const float* __restrict__ rope,
                             float* __restrict__ q, float* __restrict__ k,
                             float* __restrict__ vt) {
    int gid = blockIdx.x * blockDim.x + threadIdx.x;
    if (gid >= kSEQ * kHEADS * (kHD / 2)) return;
    int j = gid & 63;
    int h = (gid >> 6) & 15;
    int n = gid >> 10;
    int d = j * 2;
    const float* base = qkv + (size_t)n * 3 * kH;
    float q0 = base[h * kHD + d],          q1 = base[h * kHD + d + 1];
    float k0 = base[kH + h * kHD + d],     k1 = base[kH + h * kHD + d + 1];
    float v0 = base[2 * kH + h * kHD + d], v1 = base[2 * kH + h * kHD + d + 1];
    if (n >= kL) {
        const float* r = rope + (size_t)(n - kL) * kHD + d;
        float c = r[0], s = r[1];
        float t;
        t = q0 * c - q1 * s; q1 = q1 * c + q0 * s; q0 = t;
        t = k0 * c - k1 * s; k1 = k1 * c + k0 * s; k0 = t;
    }
    size_t qi = ((size_t)h * kSEQ + n) * kHD + d;
    q[qi] = q0; q[qi + 1] = q1;
    k[qi] = k0; k[qi + 1] = k1;
    size_t vi = ((size_t)h * kHD + d) * kSEQ + n;
    vt[vi] = v0; vt[vi + kSEQ] = v1;
}

// Row softmax over 2560 with scale, grid (SEQ, HEADS), 256 threads.
__global__ void softmax_rows(float* __restrict__ S) {
    float* p = S + ((size_t)blockIdx.y * kSEQ + blockIdx.x) * kSEQ;
    int tid = threadIdx.x;
    const float scale = 0.08838834764831845f;  // 128^-0.5
    float vals[10];
    float m = -3.4e38f;
    #pragma unroll
    for (int t = 0; t < 10; t++) { vals[t] = p[tid + t * 256] * scale; m = fmaxf(m, vals[t]); }
    __shared__ float sred[8];
    #pragma unroll
    for (int off = 16; off; off >>= 1) m = fmaxf(m, __shfl_xor_sync(0xffffffffu, m, off));
    if ((tid & 31) == 0) sred[tid >> 5] = m;
    __syncthreads();
    float m2 = sred[0];
    #pragma unroll
    for (int i = 1; i < 8; i++) m2 = fmaxf(m2, sred[i]);
    float sum = 0.f;
    #pragma unroll
    for (int t = 0; t < 10; t++) { vals[t] = __expf(vals[t] - m2); sum += vals[t]; }
    #pragma unroll
    for (int off = 16; off; off >>= 1) sum += __shfl_xor_sync(0xffffffffu, sum, off);
    __syncthreads();
    if ((tid & 31) == 0) sred[tid >> 5] = sum;
    __syncthreads();
    float tot = sred[0] + sred[1] + sred[2] + sred[3] + sred[4] + sred[5] + sred[6] + sred[7];
    float inv = 1.f / tot;
    #pragma unroll
    for (int t = 0; t < 10; t++) p[tid + t * 256] = vals[t] * inv;
}

// ---------------- tensor-core TF32 NT GEMM: C = A(MxK) * B(NxK)^T --------
// EPI 0: plain store
// EPI 1: bias + tanh-GELU
// EPI 2: C = res + gate[col] * (acc + optional bias[col])
__device__ __forceinline__ float gelu_tanh(float x) {
    float x3 = x * x * x;
    return 0.5f * x * (1.f + tanhf(0.7978845608028654f * (x + 0.044715f * x3)));
}

__device__ __forceinline__ uint32_t f2tf32(float x) {
    uint32_t y;
    asm("cvt.rna.tf32.f32 %0, %1;" : "=r"(y) : "f"(x));
    return y;
}

__device__ __forceinline__ void mma_tf32(float c[4], const uint32_t a[4],
                                         uint32_t b0, uint32_t b1) {
    asm volatile(
        "mma.sync.aligned.m16n8k8.row.col.f32.tf32.tf32.f32 "
        "{%0,%1,%2,%3}, {%4,%5,%6,%7}, {%8,%9}, {%0,%1,%2,%3};\n"
        : "+f"(c[0]), "+f"(c[1]), "+f"(c[2]), "+f"(c[3])
        : "r"(a[0]), "r"(a[1]), "r"(a[2]), "r"(a[3]), "r"(b0), "r"(b1));
}

// CTA tile 128x128, BK=16. 8 warps (4M x 2N), warp tile 32x64.
// Smem layout [row][k] pitch 20 words -> conflict-free fragment LDS.
template <int EPI>
__global__ __launch_bounds__(256, 2) void gemm_tc(
    const float* __restrict__ A, size_t sA,
    const float* __restrict__ B, size_t sB,
    float* __restrict__ C, size_t sC, int ldc,
    const float* __restrict__ bias,
    const float* __restrict__ gate,
    const float* __restrict__ res,
    int M, int N, int K)
{
    A += (size_t)blockIdx.z * sA;
    B += (size_t)blockIdx.z * sB;
    C += (size_t)blockIdx.z * sC;
    __shared__ __align__(16) uint32_t As[128][20];
    __shared__ __align__(16) uint32_t Bs[128][20];
    int tid  = threadIdx.x;
    int warp = tid >> 5, lane = tid & 31;
    int wm = warp >> 1, wn = warp & 1;     // 4 x 2 warp grid
    int qd = lane >> 2, s = lane & 3;      // quad row / quad lane
    const float* Ag = A + (size_t)(blockIdx.y * 128) * K;
    const float* Bg = B + (size_t)(blockIdx.x * 128) * K;

    float acc[2][8][4] = {};

    for (int k0 = 0; k0 < K; k0 += 16) {
        #pragma unroll
        for (int ld = 0; ld < 2; ld++) {
            int idx = tid + ld * 256;     // 0..511
            int row = idx >> 2;           // 0..127
            int c4  = (idx & 3) * 4;      // 0,4,8,12
            float4 a = *(const float4*)(Ag + (size_t)row * K + k0 + c4);
            uint4 ua = make_uint4(f2tf32(a.x), f2tf32(a.y), f2tf32(a.z), f2tf32(a.w));
            *(uint4*)&As[row][c4] = ua;
            float4 b = *(const float4*)(Bg + (size_t)row * K + k0 + c4);
            uint4 ub = make_uint4(f2tf32(b.x), f2tf32(b.y), f2tf32(b.z), f2tf32(b.w));
            *(uint4*)&Bs[row][c4] = ub;
        }
        __syncthreads();
        #pragma unroll
        for (int kk = 0; kk < 16; kk += 8) {
            uint32_t afr[2][4];
            #pragma unroll
            for (int tm = 0; tm < 2; tm++) {
                int r = wm * 32 + tm * 16 + qd;
                afr[tm][0] = As[r][kk + s];
                afr[tm][1] = As[r + 8][kk + s];
                afr[tm][2] = As[r][kk + 4 + s];
                afr[tm][3] = As[r + 8][kk + 4 + s];
            }
            #pragma unroll
            for (int tn = 0; tn < 8; tn++) {
                int col = wn * 64 + tn * 8 + qd;
                uint32_t b0 = Bs[col][kk + s];
                uint32_t b1 = Bs[col][kk + 4 + s];
                #pragma unroll
                for (int tm = 0; tm < 2; tm++)
                    mma_tf32(acc[tm][tn], afr[tm], b0, b1);
            }
        }
        __syncthreads();
    }

    // epilogue: c0=C[q][2s], c1=C[q][2s+1], c2=C[q+8][2s], c3=C[q+8][2s+1]
    int row_base = blockIdx.y * 128 + wm * 32 + qd;
    int col_base = blockIdx.x * 128 + wn * 64;
    #pragma unroll
    for (int tm = 0; tm < 2; tm++) {
        #pragma unroll
        for (int tn = 0; tn < 8; tn++) {
            int col = col_base + tn * 8 + 2 * s;
            #pragma unroll
            for (int half = 0; half < 2; half++) {
                int row = row_base + tm * 16 + half * 8;
                float v0 = acc[tm][tn][half * 2 + 0];
                float v1 = acc[tm][tn][half * 2 + 1];
                if (EPI == 1) {
                    v0 = gelu_tanh(v0 + bias[col]);
                    v1 = gelu_tanh(v1 + bias[col + 1]);
                } else if (EPI == 2) {
                    if (bias) { v0 += bias[col]; v1 += bias[col + 1]; }
                    const float* rp = res + (size_t)row * ldc + col;
                    v0 = rp[0] + gate[col] * v0;
                    v1 = rp[1] + gate[col + 1] * v1;
                }
                *(float2*)&C[(size_t)row * ldc + col] = make_float2(v0, v1);
            }
        }
    }
}

// ---------------- launch ----------------
extern "C" void kernel_launch(void* const* d_in, const int* in_sizes, int n_in,
                              void* d_out, int out_size) {
    const float* txt           = (const float*)d_in[0];
    const float* img           = (const float*)d_in[1];
    const float* vec           = (const float*)d_in[2];
    const float* rope          = (const float*)d_in[3];
    const float* txt_adaln_w   = (const float*)d_in[4];
    const float* txt_adaln_b   = (const float*)d_in[5];
    const float* txt_adaln_rms = (const float*)d_in[6];
    const float* img_adaln_w   = (const float*)d_in[7];
    const float* img_adaln_b   = (const float*)d_in[8];
    const float* img_adaln_rms = (const float*)d_in[9];
    const float* txt_qkv_w     = (const float*)d_in[10];
    const float* img_qkv_w     = (const float*)d_in[11];
    const float* txt_out_w     = (const float*)d_in[12];
    const float* img_out_w     = (const float*)d_in[13];
    const float* txt_norm2_w   = (const float*)d_in[14];
    const float* img_norm2_w   = (const float*)d_in[15];
    const float* txt_fc1_w     = (const float*)d_in[16];
    const float* txt_fc1_b     = (const float*)d_in[17];
    const float* txt_fc2_w     = (const float*)d_in[18];
    const float* txt_fc2_b     = (const float*)d_in[19];
    const float* img_fc1_w     = (const float*)d_in[20];
    const float* img_fc1_b     = (const float*)d_in[21];
    const float* img_fc2_w     = (const float*)d_in[22];
    const float* img_fc2_b     = (const float*)d_in[23];
    float* out = (float*)d_out;
    (void)in_sizes; (void)n_in; (void)out_size;

    float* sc = nullptr;
    cudaGetSymbolAddress((void**)&sc, g_scratch);
    float* silu = sc + OFF_SILU;
    float* mod  = sc + OFF_MOD;
    float* tmod = mod;                 // [sh_msa, sc_msa, g_msa, sh_mlp, sc_mlp, g_mlp]
    float* imod = mod + 6 * kH;
    float* xn   = sc + OFF_XN;
    float* qkv  = sc + OFF_QKV;
    float* q    = sc + OFF_Q;
    float* k    = sc + OFF_K;
    float* vt   = sc + OFF_VT;
    float* S    = sc + OFF_S;
    float* ao   = sc + OFF_AO;
    float* res  = sc + OFF_RES;
    float* h1   = sc + OFF_H1;

    // adaLN modulation params
    silu_kernel<<<8, 256>>>(vec, silu);
    adaln_gemv<<<(2 * 6 * kH) / 8, 256>>>(silu, txt_adaln_w, txt_adaln_b,
                                          img_adaln_w, img_adaln_b, mod);

    // norm1 + modulation
    norm_mod<<<kL, 256>>>(txt, xn, txt_adaln_rms, tmod, tmod + kH);
    norm_mod<<<kN, 256>>>(img, xn + (size_t)kL * kH, img_adaln_rms, imod, imod + kH);

    // QKV projections
    gemm_tc<0><<<dim3(3 * kH / 128, kL / 128), 256>>>(
        xn, 0, txt_qkv_w, 0, qkv, 0, 3 * kH, nullptr, nullptr, nullptr, kL, 3 * kH, kH);
    gemm_tc<0><<<dim3(3 * kH / 128, kN / 128), 256>>>(
        xn + (size_t)kL * kH, 0, img_qkv_w, 0, qkv + (size_t)kL * 3 * kH, 0, 3 * kH,
        nullptr, nullptr, nullptr, kN, 3 * kH, kH);

    // RoPE + head scatter (V transposed)
    rope_scatter<<<(kSEQ * kHEADS * 64) / 256, 256>>>(qkv, rope, q, k, vt);

    // joint attention: S = Q K^T (per head), softmax, O = P V
    gemm_tc<0><<<dim3(kSEQ / 128, kSEQ / 128, kHEADS), 256>>>(
        q, (size_t)kSEQ * kHD, k, (size_t)kSEQ * kHD, S, (size_t)kSEQ * kSEQ, kSEQ,
        nullptr, nullptr, nullptr, kSEQ, kSEQ, kHD);
    softmax_rows<<<dim3(kSEQ, kHEADS), 256>>>(S);
    gemm_tc<0><<<dim3(kHD / 128, kSEQ / 128, kHEADS), 256>>>(
        S, (size_t)kSEQ * kSEQ, vt, (size_t)kHD * kSEQ, ao, (size_t)kHD, kH,
        nullptr, nullptr, nullptr, kSEQ, kHD, kSEQ);

    // output projections with gated residual
    gemm_tc<2><<<dim3(kH / 128, kL / 128), 256>>>(
        ao, 0, txt_out_w, 0, res, 0, kH, nullptr, tmod + 2 * kH, txt, kL, kH, kH);
    gemm_tc<2><<<dim3(kH / 128, kN / 128), 256>>>(
        ao + (size_t)kL * kH, 0, img_out_w, 0, res + (size_t)kL * kH, 0, kH,
        nullptr, imod + 2 * kH, img, kN, kH, kH);

    // norm2 + modulation
    norm_mod<<<kL, 256>>>(res, xn, txt_norm2_w, tmod + 3 * kH, tmod + 4 * kH);
    norm_mod<<<kN, 256>>>(res + (size_t)kL * kH, xn + (size_t)kL * kH,
                          img_norm2_w, imod + 3 * kH, imod + 4 * kH);

    // txt MLP (fc1 gelu, fc2 gated residual -> d_out)
    gemm_tc<1><<<dim3(kMLP / 128, kL / 128), 256>>>(
        xn, 0, txt_fc1_w, 0, h1, 0, kMLP, txt_fc1_b, nullptr, nullptr, kL, kMLP, kH);
    gemm_tc<2><<<dim3(kH / 128, kL / 128), 256>>>(
        h1, 0, txt_fc2_w, 0, out, 0, kH, txt_fc2_b, tmod + 5 * kH, res, kL, kH, kMLP);

    // img MLP (h1 reused after txt fc2 completes in-stream)
    gemm_tc<1><<<dim3(kMLP / 128, kN / 128), 256>>>(
        xn + (size_t)kL * kH, 0, img_fc1_w, 0, h1, 0, kMLP, img_fc1_b, nullptr, nullptr,
        kN, kMLP, kH);
    gemm_tc<2><<<dim3(kH / 128, kN / 128), 256>>>(
        h1, 0, img_fc2_w, 0, out + (size_t)kL * kH, 0, kH, img_fc2_b, imod + 5 * kH,
        res + (size_t)kL * kH, kN, kH, kMLP);
}

// round 3
// speedup vs baseline: 2.5885x; 1.1563x over previous
#include <cuda_runtime.h>
#include <math.h>
#include <stdint.h>

// ---------------- problem constants ----------------
constexpr int kH     = 2048;
constexpr int kL     = 512;    // txt tokens
constexpr int kN     = 2048;   // img tokens
constexpr int kSEQ   = 2560;   // joint sequence
constexpr int kHEADS = 16;
constexpr int kHD    = 128;
constexpr int kMLP   = 8192;

// ---------------- scratch layout (single __device__ array, no allocs) ----
constexpr size_t OFF_SILU = 0;
constexpr size_t OFF_MOD  = OFF_SILU + kH;                       // 2 * 6*kH
constexpr size_t OFF_XN   = OFF_MOD  + (size_t)2 * 6 * kH;       // SEQ x H
constexpr size_t OFF_QKV  = OFF_XN   + (size_t)kSEQ * kH;        // SEQ x 3H
constexpr size_t OFF_Q    = OFF_QKV  + (size_t)kSEQ * 3 * kH;    // heads x SEQ x HD
constexpr size_t OFF_K    = OFF_Q    + (size_t)kHEADS * kSEQ * kHD;
constexpr size_t OFF_VT   = OFF_K    + (size_t)kHEADS * kSEQ * kHD;  // heads x HD x SEQ
constexpr size_t OFF_S    = OFF_VT   + (size_t)kHEADS * kHD * kSEQ;  // heads x SEQ x SEQ
constexpr size_t OFF_AO   = OFF_S    + (size_t)kHEADS * kSEQ * kSEQ; // SEQ x H
constexpr size_t OFF_RES  = OFF_AO   + (size_t)kSEQ * kH;            // SEQ x H
constexpr size_t OFF_H1   = OFF_RES  + (size_t)kSEQ * kH;            // N x MLP (reused)
constexpr size_t SCRATCH_TOTAL = OFF_H1 + (size_t)kN * kMLP;

__device__ float g_scratch[SCRATCH_TOTAL];

// ---------------- small helper kernels ----------------
__global__ void silu_kernel(const float* __restrict__ vec, float* __restrict__ out) {
    int i = blockIdx.x * blockDim.x + threadIdx.x;
    if (i < kH) {
        float v = vec[i];
        out[i] = v / (1.f + expf(-v));
    }
}

__global__ void adaln_gemv(const float* __restrict__ silu,
                           const float* __restrict__ tw, const float* __restrict__ tb,
                           const float* __restrict__ iw, const float* __restrict__ ib,
                           float* __restrict__ mod) {
    int gw = (blockIdx.x * blockDim.x + threadIdx.x) >> 5;
    int lane = threadIdx.x & 31;
    if (gw >= 2 * 6 * kH) return;
    int set = gw / (6 * kH);
    int o = gw - set * (6 * kH);
    const float* W = (set ? iw : tw) + (size_t)o * kH;
    float s = 0.f;
    for (int i = lane; i < kH; i += 32) s += silu[i] * W[i];
    #pragma unroll
    for (int off = 16; off; off >>= 1) s += __shfl_xor_sync(0xffffffffu, s, off);
    if (lane == 0) mod[(size_t)set * 6 * kH + o] = s + (set ? ib[o] : tb[o]);
}

// out = rms_norm(x, w) * (1 + sc) + sh, one block per row of 2048.
__global__ void norm_mod(const float* __restrict__ x, float* __restrict__ out,
                         const float* __restrict__ w,
                         const float* __restrict__ sh, const float* __restrict__ sc) {
    int row = blockIdx.x;
    const float* xr = x + (size_t)row * kH;
    float* orow = out + (size_t)row * kH;
    int tid = threadIdx.x;
    float ss = 0.f;
    for (int i = tid; i < kH; i += 256) { float v = xr[i]; ss += v * v; }
    __shared__ float sred[8];
    #pragma unroll
    for (int off = 16; off; off >>= 1) ss += __shfl_xor_sync(0xffffffffu, ss, off);
    if ((tid & 31) == 0) sred[tid >> 5] = ss;
    __syncthreads();
    if (tid < 8) {
        float v = sred[tid];
        #pragma unroll
        for (int off = 4; off; off >>= 1) v += __shfl_xor_sync(0xffu, v, off);
        if (tid == 0) sred[0] = v;
    }
    __syncthreads();
    float norm = rsqrtf(sred[0] * (1.f / kH) + 1e-6f);
    for (int i = tid; i < kH; i += 256)
        orow[i] = xr[i] * norm * w[i] * (1.f + sc[i]) + sh[i];
}

// Split qkv, apply RoPE to img q/k, scatter heads; v stored transposed.
// Q is pre-scaled by 128^-0.5 so softmax needs no scale.
__global__ void rope_scatter(const float* __restrict__ qkv, const float* __restrict__ rope,
                             float* __restrict__ q, float* __restrict__ k,
                             float* __restrict__ vt) {
    int gid = blockIdx.x * blockDim.x + threadIdx.x;
    if (gid >= kSEQ * kHEADS * (kHD / 2)) return;
    int j = gid & 63;
    int h = (gid >> 6) & 15;
    int n = gid >> 10;
    int d = j * 2;
    const float qscale = 0.08838834764831845f;
    const float* base = qkv + (size_t)n * 3 * kH;
    float q0 = base[h * kHD + d],          q1 = base[h * kHD + d + 1];
    float k0 = base[kH + h * kHD + d],     k1 = base[kH + h * kHD + d + 1];
    float v0 = base[2 * kH + h * kHD + d], v1 = base[2 * kH + h * kHD + d + 1];
    if (n >= kL) {
        const float* r = rope + (size_t)(n - kL) * kHD + d;
        float c = r[0], s = r[1];
        float t;
        t = q0 * c - q1 * s; q1 = q1 * c + q0 * s; q0 = t;
        t = k0 * c - k1 * s; k1 = k1 * c + k0 * s; k0 = t;
    }
    size_t qi = ((size_t)h * kSEQ + n) * kHD + d;
    q[qi] = q0 * qscale; q[qi + 1] = q1 * qscale;
    k[qi] = k0; k[qi + 1] = k1;
    size_t vi = ((size_t)h * kHD + d) * kSEQ + n;
    vt[vi] = v0; vt[vi + kSEQ] = v1;
}

// Row softmax over 2560 (Q pre-scaled), grid (SEQ, HEADS), 256 threads.
__global__ void softmax_rows(float* __restrict__ S) {
    float* p = S + ((size_t)blockIdx.y * kSEQ + blockIdx.x) * kSEQ;
    int tid = threadIdx.x;
    float vals[10];
    float m = -3.4e38f;
    #pragma unroll
    for (int t = 0; t < 10; t++) { vals[t] = p[tid + t * 256]; m = fmaxf(m, vals[t]); }
    __shared__ float sred[8];
    #pragma unroll
    for (int off = 16; off; off >>= 1) m = fmaxf(m, __shfl_xor_sync(0xffffffffu, m, off));
    if ((tid & 31) == 0) sred[tid >> 5] = m;
    __syncthreads();
    float m2 = sred[0];
    #pragma unroll
    for (int i = 1; i < 8; i++) m2 = fmaxf(m2, sred[i]);
    float sum = 0.f;
    #pragma unroll
    for (int t = 0; t < 10; t++) { vals[t] = __expf(vals[t] - m2); sum += vals[t]; }
    #pragma unroll
    for (int off = 16; off; off >>= 1) sum += __shfl_xor_sync(0xffffffffu, sum, off);
    __syncthreads();
    if ((tid & 31) == 0) sred[tid >> 5] = sum;
    __syncthreads();
    float tot = sred[0] + sred[1] + sred[2] + sred[3] + sred[4] + sred[5] + sred[6] + sred[7];
    float inv = 1.f / tot;
    #pragma unroll
    for (int t = 0; t < 10; t++) p[tid + t * 256] = vals[t] * inv;
}

// ---------------- pipelined tensor-core TF32 NT GEMM ----------------
// C = A(MxK) * B(NxK)^T
// EPI 0: plain store ; EPI 1: bias + tanh-GELU ; EPI 2: res + gate[col]*(acc+bias)
__device__ __forceinline__ float gelu_tanh(float x) {
    float x3 = x * x * x;
    return 0.5f * x * (1.f + tanhf(0.7978845608028654f * (x + 0.044715f * x3)));
}

__device__ __forceinline__ uint32_t f2tf32(float x) {
    uint32_t y;
    asm("cvt.rna.tf32.f32 %0, %1;" : "=r"(y) : "f"(x));
    return y;
}

__device__ __forceinline__ void mma_tf32(float c[4], const uint32_t a[4],
                                         uint32_t b0, uint32_t b1) {
    asm volatile(
        "mma.sync.aligned.m16n8k8.row.col.f32.tf32.tf32.f32 "
        "{%0,%1,%2,%3}, {%4,%5,%6,%7}, {%8,%9}, {%0,%1,%2,%3};\n"
        : "+f"(c[0]), "+f"(c[1]), "+f"(c[2]), "+f"(c[3])
        : "r"(a[0]), "r"(a[1]), "r"(a[2]), "r"(a[3]), "r"(b0), "r"(b1));
}

__device__ __forceinline__ void cp16(float* smem_dst, const float* gsrc) {
    uint32_t s = (uint32_t)__cvta_generic_to_shared(smem_dst);
    asm volatile("cp.async.cg.shared.global [%0], [%1], 16;\n" :: "r"(s), "l"(gsrc));
}

constexpr int STAGES = 3;
constexpr int PITCH  = 20;                       // words per row, conflict-free
constexpr int TILE_W = 128 * PITCH;              // words per (tile, stage)
constexpr size_t GEMM_SMEM = (size_t)STAGES * 2 * TILE_W * sizeof(float);  // 61440

// CTA tile 128x128, BK=16, 8 warps (4M x 2N), warp tile 32x64.
template <int EPI>
__global__ __launch_bounds__(256, 2) void gemm_tc(
    const float* __restrict__ A, size_t sA,
    const float* __restrict__ B, size_t sB,
    float* __restrict__ C, size_t sC, int ldc,
    const float* __restrict__ bias,
    const float* __restrict__ gate,
    const float* __restrict__ res,
    int M, int N, int K)
{
    A += (size_t)blockIdx.z * sA;
    B += (size_t)blockIdx.z * sB;
    C += (size_t)blockIdx.z * sC;
    extern __shared__ float smem[];
    float* As = smem;                       // [STAGES][128][PITCH]
    float* Bs = smem + STAGES * TILE_W;

    int tid  = threadIdx.x;
    int warp = tid >> 5, lane = tid & 31;
    int wm = warp >> 1, wn = warp & 1;      // 4 x 2 warp grid
    int qd = lane >> 2, s = lane & 3;       // quad row / quad lane
    const float* Ag = A + (size_t)(blockIdx.y * 128) * K;
    const float* Bg = B + (size_t)(blockIdx.x * 128) * K;

    // per-thread fill coords: 2 rows x 16B each for A and B per stage
    int r0 = tid >> 1;                      // 0..127
    int c0 = (tid & 1) * 8;                 // 0 or 8 (two float4 slots)

    float acc[2][8][4] = {};
    int nk = K >> 4;

    auto prefetch = [&](int k0i, int st) {
        int kbase = k0i * 16;
        float* as = As + st * TILE_W + r0 * PITCH + c0;
        float* bs = Bs + st * TILE_W + r0 * PITCH + c0;
        const float* ag = Ag + (size_t)r0 * K + kbase + c0;
        const float* bg = Bg + (size_t)r0 * K + kbase + c0;
        cp16(as, ag);      cp16(as + 4, ag + 4);
        cp16(bs, bg);      cp16(bs + 4, bg + 4);
    };

    // prologue
    #pragma unroll
    for (int st = 0; st < STAGES - 1; st++) {
        if (st < nk) prefetch(st, st);
        asm volatile("cp.async.commit_group;\n");
    }

    for (int k0i = 0; k0i < nk; k0i++) {
        asm volatile("cp.async.wait_group %0;\n" :: "n"(STAGES - 2));
        __syncthreads();

        const float* as = As + (k0i % STAGES) * TILE_W;
        const float* bs = Bs + (k0i % STAGES) * TILE_W;
        #pragma unroll
        for (int kk = 0; kk < 16; kk += 8) {
            uint32_t afr[2][4];
            #pragma unroll
            for (int tm = 0; tm < 2; tm++) {
                int r = wm * 32 + tm * 16 + qd;
                afr[tm][0] = f2tf32(as[r * PITCH + kk + s]);
                afr[tm][1] = f2tf32(as[(r + 8) * PITCH + kk + s]);
                afr[tm][2] = f2tf32(as[r * PITCH + kk + 4 + s]);
                afr[tm][3] = f2tf32(as[(r + 8) * PITCH + kk + 4 + s]);
            }
            #pragma unroll
            for (int tn = 0; tn < 8; tn++) {
                int col = wn * 64 + tn * 8 + qd;
                uint32_t b0 = f2tf32(bs[col * PITCH + kk + s]);
                uint32_t b1 = f2tf32(bs[col * PITCH + kk + 4 + s]);
                #pragma unroll
                for (int tm = 0; tm < 2; tm++)
                    mma_tf32(acc[tm][tn], afr[tm], b0, b1);
            }
        }

        int pf = k0i + STAGES - 1;
        if (pf < nk) prefetch(pf, pf % STAGES);
        asm volatile("cp.async.commit_group;\n");
    }

    // epilogue: c0=C[q][2s], c1=C[q][2s+1], c2=C[q+8][2s], c3=C[q+8][2s+1]
    int row_base = blockIdx.y * 128 + wm * 32 + qd;
    int col_base = blockIdx.x * 128 + wn * 64;
    #pragma unroll
    for (int tm = 0; tm < 2; tm++) {
        #pragma unroll
        for (int tn = 0; tn < 8; tn++) {
            int col = col_base + tn * 8 + 2 * s;
            #pragma unroll
            for (int half = 0; half < 2; half++) {
                int row = row_base + tm * 16 + half * 8;
                float v0 = acc[tm][tn][half * 2 + 0];
                float v1 = acc[tm][tn][half * 2 + 1];
                if (EPI == 1) {
                    v0 = gelu_tanh(v0 + bias[col]);
                    v1 = gelu_tanh(v1 + bias[col + 1]);
                } else if (EPI == 2) {
                    if (bias) { v0 += bias[col]; v1 += bias[col + 1]; }
                    const float* rp = res + (size_t)row * ldc + col;
                    v0 = rp[0] + gate[col] * v0;
                    v1 = rp[1] + gate[col + 1] * v1;
                }
                *(float2*)&C[(size_t)row * ldc + col] = make_float2(v0, v1);
            }
        }
    }
}

// ---------------- launch ----------------
extern "C" void kernel_launch(void* const* d_in, const int* in_sizes, int n_in,
                              void* d_out, int out_size) {
    const float* txt           = (const float*)d_in[0];
    const float* img           = (const float*)d_in[1];
    const float* vec           = (const float*)d_in[2];
    const float* rope          = (const float*)d_in[3];
    const float* txt_adaln_w   = (const float*)d_in[4];
    const float* txt_adaln_b   = (const float*)d_in[5];
    const float* txt_adaln_rms = (const float*)d_in[6];
    const float* img_adaln_w   = (const float*)d_in[7];
    const float* img_adaln_b   = (const float*)d_in[8];
    const float* img_adaln_rms = (const float*)d_in[9];
    const float* txt_qkv_w     = (const float*)d_in[10];
    const float* img_qkv_w     = (const float*)d_in[11];
    const float* txt_out_w     = (const float*)d_in[12];
    const float* img_out_w     = (const float*)d_in[13];
    const float* txt_norm2_w   = (const float*)d_in[14];
    const float* img_norm2_w   = (const float*)d_in[15];
    const float* txt_fc1_w     = (const float*)d_in[16];
    const float* txt_fc1_b     = (const float*)d_in[17];
    const float* txt_fc2_w     = (const float*)d_in[18];
    const float* txt_fc2_b     = (const float*)d_in[19];
    const float* img_fc1_w     = (const float*)d_in[20];
    const float* img_fc1_b     = (const float*)d_in[21];
    const float* img_fc2_w     = (const float*)d_in[22];
    const float* img_fc2_b     = (const float*)d_in[23];
    float* out = (float*)d_out;
    (void)in_sizes; (void)n_in; (void)out_size;

    static bool attr_done = false;
    if (!attr_done) {
        cudaFuncSetAttribute(gemm_tc<0>, cudaFuncAttributeMaxDynamicSharedMemorySize, (int)GEMM_SMEM);
        cudaFuncSetAttribute(gemm_tc<1>, cudaFuncAttributeMaxDynamicSharedMemorySize, (int)GEMM_SMEM);
        cudaFuncSetAttribute(gemm_tc<2>, cudaFuncAttributeMaxDynamicSharedMemorySize, (int)GEMM_SMEM);
        attr_done = true;
    }

    float* sc = nullptr;
    cudaGetSymbolAddress((void**)&sc, g_scratch);
    float* silu = sc + OFF_SILU;
    float* mod  = sc + OFF_MOD;
    float* tmod = mod;                 // [sh_msa, sc_msa, g_msa, sh_mlp, sc_mlp, g_mlp]
    float* imod = mod + 6 * kH;
    float* xn   = sc + OFF_XN;
    float* qkv  = sc + OFF_QKV;
    float* q    = sc + OFF_Q;
    float* k    = sc + OFF_K;
    float* vt   = sc + OFF_VT;
    float* S    = sc + OFF_S;
    float* ao   = sc + OFF_AO;
    float* res  = sc + OFF_RES;
    float* h1   = sc + OFF_H1;

    // adaLN modulation params
    silu_kernel<<<8, 256>>>(vec, silu);
    adaln_gemv<<<(2 * 6 * kH) / 8, 256>>>(silu, txt_adaln_w, txt_adaln_b,
                                          img_adaln_w, img_adaln_b, mod);

    // norm1 + modulation
    norm_mod<<<kL, 256>>>(txt, xn, txt_adaln_rms, tmod, tmod + kH);
    norm_mod<<<kN, 256>>>(img, xn + (size_t)kL * kH, img_adaln_rms, imod, imod + kH);

    // QKV projections
    gemm_tc<0><<<dim3(3 * kH / 128, kL / 128), 256, GEMM_SMEM>>>(
        xn, 0, txt_qkv_w, 0, qkv, 0, 3 * kH, nullptr, nullptr, nullptr, kL, 3 * kH, kH);
    gemm_tc<0><<<dim3(3 * kH / 128, kN / 128), 256, GEMM_SMEM>>>(
        xn + (size_t)kL * kH, 0, img_qkv_w, 0, qkv + (size_t)kL * 3 * kH, 0, 3 * kH,
        nullptr, nullptr, nullptr, kN, 3 * kH, kH);

    // RoPE + head scatter (V transposed, Q pre-scaled)
    rope_scatter<<<(kSEQ * kHEADS * 64) / 256, 256>>>(qkv, rope, q, k, vt);

    // joint attention: S = Q K^T (per head), softmax, O = P V
    gemm_tc<0><<<dim3(kSEQ / 128, kSEQ / 128, kHEADS), 256, GEMM_SMEM>>>(
        q, (size_t)kSEQ * kHD, k, (size_t)kSEQ * kHD, S, (size_t)kSEQ * kSEQ, kSEQ,
        nullptr, nullptr, nullptr, kSEQ, kSEQ, kHD);
    softmax_rows<<<dim3(kSEQ, kHEADS), 256>>>(S);
    gemm_tc<0><<<dim3(kHD / 128, kSEQ / 128, kHEADS), 256, GEMM_SMEM>>>(
        S, (size_t)kSEQ * kSEQ, vt, (size_t)kHD * kSEQ, ao, (size_t)kHD, kH,
        nullptr, nullptr, nullptr, kSEQ, kHD, kSEQ);

    // output projections with gated residual
    gemm_tc<2><<<dim3(kH / 128, kL / 128), 256, GEMM_SMEM>>>(
        ao, 0, txt_out_w, 0, res, 0, kH, nullptr, tmod + 2 * kH, txt, kL, kH, kH);
    gemm_tc<2><<<dim3(kH / 128, kN / 128), 256, GEMM_SMEM>>>(
        ao + (size_t)kL * kH, 0, img_out_w, 0, res + (size_t)kL * kH, 0, kH,
        nullptr, imod + 2 * kH, img, kN, kH, kH);

    // norm2 + modulation
    norm_mod<<<kL, 256>>>(res, xn, txt_norm2_w, tmod + 3 * kH, tmod + 4 * kH);
    norm_mod<<<kN, 256>>>(res + (size_t)kL * kH, xn + (size_t)kL * kH,
                          img_norm2_w, imod + 3 * kH, imod + 4 * kH);

    // txt MLP (fc1 gelu, fc2 gated residual -> d_out)
    gemm_tc<1><<<dim3(kMLP / 128, kL / 128), 256, GEMM_SMEM>>>(
        xn, 0, txt_fc1_w, 0, h1, 0, kMLP, txt_fc1_b, nullptr, nullptr, kL, kMLP, kH);
    gemm_tc<2><<<dim3(kH / 128, kL / 128), 256, GEMM_SMEM>>>(
        h1, 0, txt_fc2_w, 0, out, 0, kH, txt_fc2_b, tmod + 5 * kH, res, kL, kH, kMLP);

    // img MLP (h1 reused after txt fc2 completes in-stream)
    gemm_tc<1><<<dim3(kMLP / 128, kN / 128), 256, GEMM_SMEM>>>(
        xn + (size_t)kL * kH, 0, img_fc1_w, 0, h1, 0, kMLP, img_fc1_b, nullptr, nullptr,
        kN, kMLP, kH);
    gemm_tc<2><<<dim3(kH / 128, kN / 128), 256, GEMM_SMEM>>>(
        h1, 0, img_fc2_w, 0, out + (size_t)kL * kH, 0, kH, img_fc2_b, imod + 5 * kH,
        res + (size_t)kL * kH, kN, kH, kMLP);
}

// round 4
// speedup vs baseline: 2.7605x; 1.0665x over previous
#include <cuda_runtime.h>
#include <math.h>
#include <stdint.h>

// ---------------- problem constants ----------------
constexpr int kH     = 2048;
constexpr int kL     = 512;    // txt tokens
constexpr int kN     = 2048;   // img tokens
constexpr int kSEQ   = 2560;   // joint sequence
constexpr int kHEADS = 16;
constexpr int kHD    = 128;
constexpr int kMLP   = 8192;

// ---------------- scratch layout (single __device__ array, no allocs) ----
constexpr size_t OFF_SILU = 0;
constexpr size_t OFF_MOD  = OFF_SILU + kH;                       // 2 * 6*kH
constexpr size_t OFF_XN   = OFF_MOD  + (size_t)2 * 6 * kH;       // SEQ x H
constexpr size_t OFF_QKV  = OFF_XN   + (size_t)kSEQ * kH;        // SEQ x 3H
constexpr size_t OFF_Q    = OFF_QKV  + (size_t)kSEQ * 3 * kH;    // heads x SEQ x HD
constexpr size_t OFF_K    = OFF_Q    + (size_t)kHEADS * kSEQ * kHD;
constexpr size_t OFF_VT   = OFF_K    + (size_t)kHEADS * kSEQ * kHD;  // heads x HD x SEQ
constexpr size_t OFF_S    = OFF_VT   + (size_t)kHEADS * kHD * kSEQ;  // heads x SEQ x SEQ
constexpr size_t OFF_AO   = OFF_S    + (size_t)kHEADS * kSEQ * kSEQ; // SEQ x H
constexpr size_t OFF_RES  = OFF_AO   + (size_t)kSEQ * kH;            // SEQ x H
constexpr size_t OFF_H1   = OFF_RES  + (size_t)kSEQ * kH;            // N x MLP (reused)
constexpr size_t SCRATCH_TOTAL = OFF_H1 + (size_t)kN * kMLP;

__device__ float g_scratch[SCRATCH_TOTAL];

// ---------------- small helper kernels ----------------
__global__ void silu_kernel(const float* __restrict__ vec, float* __restrict__ out) {
    int i = blockIdx.x * blockDim.x + threadIdx.x;
    if (i < kH) {
        float v = vec[i];
        out[i] = v / (1.f + expf(-v));
    }
}

__global__ void adaln_gemv(const float* __restrict__ silu,
                           const float* __restrict__ tw, const float* __restrict__ tb,
                           const float* __restrict__ iw, const float* __restrict__ ib,
                           float* __restrict__ mod) {
    int gw = (blockIdx.x * blockDim.x + threadIdx.x) >> 5;
    int lane = threadIdx.x & 31;
    if (gw >= 2 * 6 * kH) return;
    int set = gw / (6 * kH);
    int o = gw - set * (6 * kH);
    const float* W = (set ? iw : tw) + (size_t)o * kH;
    float s = 0.f;
    for (int i = lane; i < kH; i += 32) s += silu[i] * W[i];
    #pragma unroll
    for (int off = 16; off; off >>= 1) s += __shfl_xor_sync(0xffffffffu, s, off);
    if (lane == 0) mod[(size_t)set * 6 * kH + o] = s + (set ? ib[o] : tb[o]);
}

// out = rms_norm(x, w) * (1 + sc) + sh, one block per row of 2048.
__global__ void norm_mod(const float* __restrict__ x, float* __restrict__ out,
                         const float* __restrict__ w,
                         const float* __restrict__ sh, const float* __restrict__ sc) {
    int row = blockIdx.x;
    const float* xr = x + (size_t)row * kH;
    float* orow = out + (size_t)row * kH;
    int tid = threadIdx.x;
    float ss = 0.f;
    for (int i = tid; i < kH; i += 256) { float v = xr[i]; ss += v * v; }
    __shared__ float sred[8];
    #pragma unroll
    for (int off = 16; off; off >>= 1) ss += __shfl_xor_sync(0xffffffffu, ss, off);
    if ((tid & 31) == 0) sred[tid >> 5] = ss;
    __syncthreads();
    if (tid < 8) {
        float v = sred[tid];
        #pragma unroll
        for (int off = 4; off; off >>= 1) v += __shfl_xor_sync(0xffu, v, off);
        if (tid == 0) sred[0] = v;
    }
    __syncthreads();
    float norm = rsqrtf(sred[0] * (1.f / kH) + 1e-6f);
    for (int i = tid; i < kH; i += 256)
        orow[i] = xr[i] * norm * w[i] * (1.f + sc[i]) + sh[i];
}

// Split qkv, apply RoPE to img q/k, scatter heads; v stored transposed.
// Q is pre-scaled by 128^-0.5 so softmax needs no scale.
__global__ void rope_scatter(const float* __restrict__ qkv, const float* __restrict__ rope,
                             float* __restrict__ q, float* __restrict__ k,
                             float* __restrict__ vt) {
    int gid = blockIdx.x * blockDim.x + threadIdx.x;
    if (gid >= kSEQ * kHEADS * (kHD / 2)) return;
    int j = gid & 63;
    int h = (gid >> 6) & 15;
    int n = gid >> 10;
    int d = j * 2;
    const float qscale = 0.08838834764831845f;
    const float* base = qkv + (size_t)n * 3 * kH;
    float q0 = base[h * kHD + d],          q1 = base[h * kHD + d + 1];
    float k0 = base[kH + h * kHD + d],     k1 = base[kH + h * kHD + d + 1];
    float v0 = base[2 * kH + h * kHD + d], v1 = base[2 * kH + h * kHD + d + 1];
    if (n >= kL) {
        const float* r = rope + (size_t)(n - kL) * kHD + d;
        float c = r[0], s = r[1];
        float t;
        t = q0 * c - q1 * s; q1 = q1 * c + q0 * s; q0 = t;
        t = k0 * c - k1 * s; k1 = k1 * c + k0 * s; k0 = t;
    }
    size_t qi = ((size_t)h * kSEQ + n) * kHD + d;
    q[qi] = q0 * qscale; q[qi + 1] = q1 * qscale;
    k[qi] = k0; k[qi + 1] = k1;
    size_t vi = ((size_t)h * kHD + d) * kSEQ + n;
    vt[vi] = v0; vt[vi + kSEQ] = v1;
}

// Row softmax over 2560 (Q pre-scaled), grid (SEQ, HEADS), 256 threads.
__global__ void softmax_rows(float* __restrict__ S) {
    float* p = S + ((size_t)blockIdx.y * kSEQ + blockIdx.x) * kSEQ;
    int tid = threadIdx.x;
    float vals[10];
    float m = -3.4e38f;
    #pragma unroll
    for (int t = 0; t < 10; t++) { vals[t] = p[tid + t * 256]; m = fmaxf(m, vals[t]); }
    __shared__ float sred[8];
    #pragma unroll
    for (int off = 16; off; off >>= 1) m = fmaxf(m, __shfl_xor_sync(0xffffffffu, m, off));
    if ((tid & 31) == 0) sred[tid >> 5] = m;
    __syncthreads();
    float m2 = sred[0];
    #pragma unroll
    for (int i = 1; i < 8; i++) m2 = fmaxf(m2, sred[i]);
    float sum = 0.f;
    #pragma unroll
    for (int t = 0; t < 10; t++) { vals[t] = __expf(vals[t] - m2); sum += vals[t]; }
    #pragma unroll
    for (int off = 16; off; off >>= 1) sum += __shfl_xor_sync(0xffffffffu, sum, off);
    __syncthreads();
    if ((tid & 31) == 0) sred[tid >> 5] = sum;
    __syncthreads();
    float tot = sred[0] + sred[1] + sred[2] + sred[3] + sred[4] + sred[5] + sred[6] + sred[7];
    float inv = 1.f / tot;
    #pragma unroll
    for (int t = 0; t < 10; t++) p[tid + t * 256] = vals[t] * inv;
}

// ---------------- pipelined tensor-core TF32 NT GEMM ----------------
// C = A(MxK) * B(NxK)^T
// EPI 0: plain store ; EPI 1: bias + tanh-GELU ; EPI 2: res + gate[col]*(acc+bias)
__device__ __forceinline__ float gelu_tanh(float x) {
    float x3 = x * x * x;
    return 0.5f * x * (1.f + tanhf(0.7978845608028654f * (x + 0.044715f * x3)));
}

__device__ __forceinline__ uint32_t f2tf32(float x) {
    uint32_t y;
    asm("cvt.rna.tf32.f32 %0, %1;" : "=r"(y) : "f"(x));
    return y;
}

__device__ __forceinline__ void mma_tf32(float c[4], const uint32_t a[4],
                                         uint32_t b0, uint32_t b1) {
    asm volatile(
        "mma.sync.aligned.m16n8k8.row.col.f32.tf32.tf32.f32 "
        "{%0,%1,%2,%3}, {%4,%5,%6,%7}, {%8,%9}, {%0,%1,%2,%3};\n"
        : "+f"(c[0]), "+f"(c[1]), "+f"(c[2]), "+f"(c[3])
        : "r"(a[0]), "r"(a[1]), "r"(a[2]), "r"(a[3]), "r"(b0), "r"(b1));
}

__device__ __forceinline__ void cp16(float* smem_dst, const float* gsrc) {
    uint32_t s = (uint32_t)__cvta_generic_to_shared(smem_dst);
    asm volatile("cp.async.cg.shared.global [%0], [%1], 16;\n" :: "r"(s), "l"(gsrc));
}

constexpr int STAGES = 3;
constexpr int PITCH  = 20;                       // words per row, conflict-free
constexpr int TILE_W = 128 * PITCH;              // words per (tile, stage)
constexpr size_t GEMM_SMEM = (size_t)STAGES * 2 * TILE_W * sizeof(float);  // 61440

// CTA tile 128x128, BK=16, 4 warps (2M x 2N), warp tile 64x64, 128 threads.
template <int EPI>
__global__ __launch_bounds__(128, 2) void gemm_tc(
    const float* __restrict__ A, size_t sA,
    const float* __restrict__ B, size_t sB,
    float* __restrict__ C, size_t sC, int ldc,
    const float* __restrict__ bias,
    const float* __restrict__ gate,
    const float* __restrict__ res,
    int M, int N, int K)
{
    A += (size_t)blockIdx.z * sA;
    B += (size_t)blockIdx.z * sB;
    C += (size_t)blockIdx.z * sC;
    extern __shared__ float smem[];
    float* As = smem;                       // [STAGES][128][PITCH]
    float* Bs = smem + STAGES * TILE_W;

    int tid  = threadIdx.x;
    int warp = tid >> 5, lane = tid & 31;
    int wm = warp >> 1, wn = warp & 1;      // 2 x 2 warp grid, 64x64 tiles
    int qd = lane >> 2, s = lane & 3;       // quad row / quad lane
    const float* Ag = A + (size_t)(blockIdx.y * 128) * K;
    const float* Bg = B + (size_t)(blockIdx.x * 128) * K;

    // fill mapping: i in 0..3, row = i*32 + (tid>>2), c4 = (tid&3)*4.
    // Per-warp STS covers each bank exactly 4x (4-phase minimum, no conflicts);
    // gmem reads are 4 lanes x 16B = 64B contiguous per row.
    int frow = tid >> 2;
    int fc4  = (tid & 3) * 4;

    float acc[4][8][4] = {};
    int nk = K >> 4;

    auto prefetch = [&](int k0i, int st) {
        int kbase = k0i * 16 + fc4;
        float* as = As + st * TILE_W;
        float* bs = Bs + st * TILE_W;
        #pragma unroll
        for (int i = 0; i < 4; i++) {
            int row = i * 32 + frow;
            cp16(as + row * PITCH + fc4, Ag + (size_t)row * K + kbase);
            cp16(bs + row * PITCH + fc4, Bg + (size_t)row * K + kbase);
        }
    };

    // prologue
    #pragma unroll
    for (int st = 0; st < STAGES - 1; st++) {
        if (st < nk) prefetch(st, st);
        asm volatile("cp.async.commit_group;\n");
    }

    for (int k0i = 0; k0i < nk; k0i++) {
        asm volatile("cp.async.wait_group %0;\n" :: "n"(STAGES - 2));
        __syncthreads();

        const float* as = As + (k0i % STAGES) * TILE_W;
        const float* bs = Bs + (k0i % STAGES) * TILE_W;
        #pragma unroll
        for (int kk = 0; kk < 16; kk += 8) {
            uint32_t afr[4][4];
            #pragma unroll
            for (int tm = 0; tm < 4; tm++) {
                int r = wm * 64 + tm * 16 + qd;
                afr[tm][0] = f2tf32(as[r * PITCH + kk + s]);
                afr[tm][1] = f2tf32(as[(r + 8) * PITCH + kk + s]);
                afr[tm][2] = f2tf32(as[r * PITCH + kk + 4 + s]);
                afr[tm][3] = f2tf32(as[(r + 8) * PITCH + kk + 4 + s]);
            }
            #pragma unroll
            for (int tn = 0; tn < 8; tn++) {
                int col = wn * 64 + tn * 8 + qd;
                uint32_t b0 = f2tf32(bs[col * PITCH + kk + s]);
                uint32_t b1 = f2tf32(bs[col * PITCH + kk + 4 + s]);
                #pragma unroll
                for (int tm = 0; tm < 4; tm++)
                    mma_tf32(acc[tm][tn], afr[tm], b0, b1);
            }
        }

        int pf = k0i + STAGES - 1;
        if (pf < nk) prefetch(pf, pf % STAGES);
        asm volatile("cp.async.commit_group;\n");
    }

    // epilogue: c0=C[q][2s], c1=C[q][2s+1], c2=C[q+8][2s], c3=C[q+8][2s+1]
    int row_base = blockIdx.y * 128 + wm * 64 + qd;
    int col_base = blockIdx.x * 128 + wn * 64;
    #pragma unroll
    for (int tm = 0; tm < 4; tm++) {
        #pragma unroll
        for (int tn = 0; tn < 8; tn++) {
            int col = col_base + tn * 8 + 2 * s;
            #pragma unroll
            for (int half = 0; half < 2; half++) {
                int row = row_base + tm * 16 + half * 8;
                float v0 = acc[tm][tn][half * 2 + 0];
                float v1 = acc[tm][tn][half * 2 + 1];
                if (EPI == 1) {
                    v0 = gelu_tanh(v0 + bias[col]);
                    v1 = gelu_tanh(v1 + bias[col + 1]);
                } else if (EPI == 2) {
                    if (bias) { v0 += bias[col]; v1 += bias[col + 1]; }
                    const float* rp = res + (size_t)row * ldc + col;
                    v0 = rp[0] + gate[col] * v0;
                    v1 = rp[1] + gate[col + 1] * v1;
                }
                *(float2*)&C[(size_t)row * ldc + col] = make_float2(v0, v1);
            }
        }
    }
}

// ---------------- launch ----------------
extern "C" void kernel_launch(void* const* d_in, const int* in_sizes, int n_in,
                              void* d_out, int out_size) {
    const float* txt           = (const float*)d_in[0];
    const float* img           = (const float*)d_in[1];
    const float* vec           = (const float*)d_in[2];
    const float* rope          = (const float*)d_in[3];
    const float* txt_adaln_w   = (const float*)d_in[4];
    const float* txt_adaln_b   = (const float*)d_in[5];
    const float* txt_adaln_rms = (const float*)d_in[6];
    const float* img_adaln_w   = (const float*)d_in[7];
    const float* img_adaln_b   = (const float*)d_in[8];
    const float* img_adaln_rms = (const float*)d_in[9];
    const float* txt_qkv_w     = (const float*)d_in[10];
    const float* img_qkv_w     = (const float*)d_in[11];
    const float* txt_out_w     = (const float*)d_in[12];
    const float* img_out_w     = (const float*)d_in[13];
    const float* txt_norm2_w   = (const float*)d_in[14];
    const float* img_norm2_w   = (const float*)d_in[15];
    const float* txt_fc1_w     = (const float*)d_in[16];
    const float* txt_fc1_b     = (const float*)d_in[17];
    const float* txt_fc2_w     = (const float*)d_in[18];
    const float* txt_fc2_b     = (const float*)d_in[19];
    const float* img_fc1_w     = (const float*)d_in[20];
    const float* img_fc1_b     = (const float*)d_in[21];
    const float* img_fc2_w     = (const float*)d_in[22];
    const float* img_fc2_b     = (const float*)d_in[23];
    float* out = (float*)d_out;
    (void)in_sizes; (void)n_in; (void)out_size;

    static bool attr_done = false;
    if (!attr_done) {
        cudaFuncSetAttribute(gemm_tc<0>, cudaFuncAttributeMaxDynamicSharedMemorySize, (int)GEMM_SMEM);
        cudaFuncSetAttribute(gemm_tc<1>, cudaFuncAttributeMaxDynamicSharedMemorySize, (int)GEMM_SMEM);
        cudaFuncSetAttribute(gemm_tc<2>, cudaFuncAttributeMaxDynamicSharedMemorySize, (int)GEMM_SMEM);
        attr_done = true;
    }

    float* sc = nullptr;
    cudaGetSymbolAddress((void**)&sc, g_scratch);
    float* silu = sc + OFF_SILU;
    float* mod  = sc + OFF_MOD;
    float* tmod = mod;                 // [sh_msa, sc_msa, g_msa, sh_mlp, sc_mlp, g_mlp]
    float* imod = mod + 6 * kH;
    float* xn   = sc + OFF_XN;
    float* qkv  = sc + OFF_QKV;
    float* q    = sc + OFF_Q;
    float* k    = sc + OFF_K;
    float* vt   = sc + OFF_VT;
    float* S    = sc + OFF_S;
    float* ao   = sc + OFF_AO;
    float* res  = sc + OFF_RES;
    float* h1   = sc + OFF_H1;

    // adaLN modulation params
    silu_kernel<<<8, 256>>>(vec, silu);
    adaln_gemv<<<(2 * 6 * kH) / 8, 256>>>(silu, txt_adaln_w, txt_adaln_b,
                                          img_adaln_w, img_adaln_b, mod);

    // norm1 + modulation
    norm_mod<<<kL, 256>>>(txt, xn, txt_adaln_rms, tmod, tmod + kH);
    norm_mod<<<kN, 256>>>(img, xn + (size_t)kL * kH, img_adaln_rms, imod, imod + kH);

    // QKV projections
    gemm_tc<0><<<dim3(3 * kH / 128, kL / 128), 128, GEMM_SMEM>>>(
        xn, 0, txt_qkv_w, 0, qkv, 0, 3 * kH, nullptr, nullptr, nullptr, kL, 3 * kH, kH);
    gemm_tc<0><<<dim3(3 * kH / 128, kN / 128), 128, GEMM_SMEM>>>(
        xn + (size_t)kL * kH, 0, img_qkv_w, 0, qkv + (size_t)kL * 3 * kH, 0, 3 * kH,
        nullptr, nullptr, nullptr, kN, 3 * kH, kH);

    // RoPE + head scatter (V transposed, Q pre-scaled)
    rope_scatter<<<(kSEQ * kHEADS * 64) / 256, 256>>>(qkv, rope, q, k, vt);

    // joint attention: S = Q K^T (per head), softmax, O = P V
    gemm_tc<0><<<dim3(kSEQ / 128, kSEQ / 128, kHEADS), 128, GEMM_SMEM>>>(
        q, (size_t)kSEQ * kHD, k, (size_t)kSEQ * kHD, S, (size_t)kSEQ * kSEQ, kSEQ,
        nullptr, nullptr, nullptr, kSEQ, kSEQ, kHD);
    softmax_rows<<<dim3(kSEQ, kHEADS), 256>>>(S);
    gemm_tc<0><<<dim3(kHD / 128, kSEQ / 128, kHEADS), 128, GEMM_SMEM>>>(
        S, (size_t)kSEQ * kSEQ, vt, (size_t)kHD * kSEQ, ao, (size_t)kHD, kH,
        nullptr, nullptr, nullptr, kSEQ, kHD, kSEQ);

    // output projections with gated residual
    gemm_tc<2><<<dim3(kH / 128, kL / 128), 128, GEMM_SMEM>>>(
        ao, 0, txt_out_w, 0, res, 0, kH, nullptr, tmod + 2 * kH, txt, kL, kH, kH);
    gemm_tc<2><<<dim3(kH / 128, kN / 128), 128, GEMM_SMEM>>>(
        ao + (size_t)kL * kH, 0, img_out_w, 0, res + (size_t)kL * kH, 0, kH,
        nullptr, imod + 2 * kH, img, kN, kH, kH);

    // norm2 + modulation
    norm_mod<<<kL, 256>>>(res, xn, txt_norm2_w, tmod + 3 * kH, tmod + 4 * kH);
    norm_mod<<<kN, 256>>>(res + (size_t)kL * kH, xn + (size_t)kL * kH,
                          img_norm2_w, imod + 3 * kH, imod + 4 * kH);

    // txt MLP (fc1 gelu, fc2 gated residual -> d_out)
    gemm_tc<1><<<dim3(kMLP / 128, kL / 128), 128, GEMM_SMEM>>>(
        xn, 0, txt_fc1_w, 0, h1, 0, kMLP, txt_fc1_b, nullptr, nullptr, kL, kMLP, kH);
    gemm_tc<2><<<dim3(kH / 128, kL / 128), 128, GEMM_SMEM>>>(
        h1, 0, txt_fc2_w, 0, out, 0, kH, txt_fc2_b, tmod + 5 * kH, res, kL, kH, kMLP);

    // img MLP (h1 reused after txt fc2 completes in-stream)
    gemm_tc<1><<<dim3(kMLP / 128, kN / 128), 128, GEMM_SMEM>>>(
        xn + (size_t)kL * kH, 0, img_fc1_w, 0, h1, 0, kMLP, img_fc1_b, nullptr, nullptr,
        kN, kMLP, kH);
    gemm_tc<2><<<dim3(kH / 128, kN / 128), 128, GEMM_SMEM>>>(
        h1, 0, img_fc2_w, 0, out + (size_t)kL * kH, 0, kH, img_fc2_b, imod + 5 * kH,
        res + (size_t)kL * kH, kN, kH, kMLP);
}

// round 6
// speedup vs baseline: 3.2917x; 1.1924x over previous
#include <cuda_runtime.h>
#include <math.h>
#include <stdint.h>

// ---------------- problem constants ----------------
constexpr int kH     = 2048;
constexpr int kL     = 512;    // txt tokens
constexpr int kN     = 2048;   // img tokens
constexpr int kSEQ   = 2560;   // joint sequence
constexpr int kHEADS = 16;
constexpr int kHD    = 128;
constexpr int kMLP   = 8192;

// ---------------- scratch layout (single __device__ array, no allocs) ----
constexpr size_t OFF_SILU = 0;
constexpr size_t OFF_MOD  = OFF_SILU + kH;
constexpr size_t OFF_XN   = OFF_MOD  + (size_t)2 * 6 * kH;
constexpr size_t OFF_QKV  = OFF_XN   + (size_t)kSEQ * kH;
constexpr size_t OFF_Q    = OFF_QKV  + (size_t)kSEQ * 3 * kH;
constexpr size_t OFF_K    = OFF_Q    + (size_t)kHEADS * kSEQ * kHD;
constexpr size_t OFF_VT   = OFF_K    + (size_t)kHEADS * kSEQ * kHD;
constexpr size_t OFF_S    = OFF_VT   + (size_t)kHEADS * kHD * kSEQ;
constexpr size_t OFF_AO   = OFF_S    + (size_t)kHEADS * kSEQ * kSEQ;
constexpr size_t OFF_RES  = OFF_AO   + (size_t)kSEQ * kH;
constexpr size_t OFF_H1   = OFF_RES  + (size_t)kSEQ * kH;
constexpr size_t SCRATCH_TOTAL = OFF_H1 + (size_t)kN * kMLP;

__device__ __align__(256) float g_scratch[SCRATCH_TOTAL];

// round fp32 -> tf32 (rna), result kept in fp32 container
__device__ __forceinline__ float rnd_tf32(float x) {
    uint32_t y;
    asm("cvt.rna.tf32.f32 %0, %1;" : "=r"(y) : "f"(x));
    return __uint_as_float(y);
}

// ---------------- small helper kernels ----------------
__global__ void silu_kernel(const float* __restrict__ vec, float* __restrict__ out) {
    int i = blockIdx.x * blockDim.x + threadIdx.x;
    if (i < kH) {
        float v = vec[i];
        out[i] = v / (1.f + expf(-v));
    }
}

__global__ void adaln_gemv(const float* __restrict__ silu,
                           const float* __restrict__ tw, const float* __restrict__ tb,
                           const float* __restrict__ iw, const float* __restrict__ ib,
                           float* __restrict__ mod) {
    int gw = (blockIdx.x * blockDim.x + threadIdx.x) >> 5;
    int lane = threadIdx.x & 31;
    if (gw >= 2 * 6 * kH) return;
    int set = gw / (6 * kH);
    int o = gw - set * (6 * kH);
    const float* W = (set ? iw : tw) + (size_t)o * kH;
    float s = 0.f;
    for (int i = lane; i < kH; i += 32) s += silu[i] * W[i];
    #pragma unroll
    for (int off = 16; off; off >>= 1) s += __shfl_xor_sync(0xffffffffu, s, off);
    if (lane == 0) mod[(size_t)set * 6 * kH + o] = s + (set ? ib[o] : tb[o]);
}

// out = tf32_round(rms_norm(x, w) * (1 + sc) + sh) -- output feeds GEMM A.
__global__ void norm_mod(const float* __restrict__ x, float* __restrict__ out,
                         const float* __restrict__ w,
                         const float* __restrict__ sh, const float* __restrict__ sc) {
    int row = blockIdx.x;
    const float* xr = x + (size_t)row * kH;
    float* orow = out + (size_t)row * kH;
    int tid = threadIdx.x;
    float ss = 0.f;
    for (int i = tid; i < kH; i += 256) { float v = xr[i]; ss += v * v; }
    __shared__ float sred[8];
    #pragma unroll
    for (int off = 16; off; off >>= 1) ss += __shfl_xor_sync(0xffffffffu, ss, off);
    if ((tid & 31) == 0) sred[tid >> 5] = ss;
    __syncthreads();
    if (tid < 8) {
        float v = sred[tid];
        #pragma unroll
        for (int off = 4; off; off >>= 1) v += __shfl_xor_sync(0xffu, v, off);
        if (tid == 0) sred[0] = v;
    }
    __syncthreads();
    float norm = rsqrtf(sred[0] * (1.f / kH) + 1e-6f);
    for (int i = tid; i < kH; i += 256)
        orow[i] = rnd_tf32(xr[i] * norm * w[i] * (1.f + sc[i]) + sh[i]);
}

// Split qkv, apply RoPE to img q/k, scatter heads; v stored transposed.
// Q pre-scaled by 128^-0.5; all outputs tf32-rounded (they feed GEMMs).
__global__ void rope_scatter(const float* __restrict__ qkv, const float* __restrict__ rope,
                             float* __restrict__ q, float* __restrict__ k,
                             float* __restrict__ vt) {
    int gid = blockIdx.x * blockDim.x + threadIdx.x;
    if (gid >= kSEQ * kHEADS * (kHD / 2)) return;
    int j = gid & 63;
    int h = (gid >> 6) & 15;
    int n = gid >> 10;
    int d = j * 2;
    const float qscale = 0.08838834764831845f;
    const float* base = qkv + (size_t)n * 3 * kH;
    float q0 = base[h * kHD + d],          q1 = base[h * kHD + d + 1];
    float k0 = base[kH + h * kHD + d],     k1 = base[kH + h * kHD + d + 1];
    float v0 = base[2 * kH + h * kHD + d], v1 = base[2 * kH + h * kHD + d + 1];
    if (n >= kL) {
        const float* r = rope + (size_t)(n - kL) * kHD + d;
        float c = r[0], s = r[1];
        float t;
        t = q0 * c - q1 * s; q1 = q1 * c + q0 * s; q0 = t;
        t = k0 * c - k1 * s; k1 = k1 * c + k0 * s; k0 = t;
    }
    size_t qi = ((size_t)h * kSEQ + n) * kHD + d;
    q[qi] = rnd_tf32(q0 * qscale); q[qi + 1] = rnd_tf32(q1 * qscale);
    k[qi] = rnd_tf32(k0); k[qi + 1] = rnd_tf32(k1);
    size_t vi = ((size_t)h * kHD + d) * kSEQ + n;
    vt[vi] = rnd_tf32(v0); vt[vi + kSEQ] = rnd_tf32(v1);
}

// Row softmax over 2560 (Q pre-scaled); output tf32-rounded (feeds PV GEMM).
__global__ void softmax_rows(float* __restrict__ S) {
    float* p = S + ((size_t)blockIdx.y * kSEQ + blockIdx.x) * kSEQ;
    int tid = threadIdx.x;
    float vals[10];
    float m = -3.4e38f;
    #pragma unroll
    for (int t = 0; t < 10; t++) { vals[t] = p[tid + t * 256]; m = fmaxf(m, vals[t]); }
    __shared__ float sred[8];
    #pragma unroll
    for (int off = 16; off; off >>= 1) m = fmaxf(m, __shfl_xor_sync(0xffffffffu, m, off));
    if ((tid & 31) == 0) sred[tid >> 5] = m;
    __syncthreads();
    float m2 = sred[0];
    #pragma unroll
    for (int i = 1; i < 8; i++) m2 = fmaxf(m2, sred[i]);
    float sum = 0.f;
    #pragma unroll
    for (int t = 0; t < 10; t++) { vals[t] = __expf(vals[t] - m2); sum += vals[t]; }
    #pragma unroll
    for (int off = 16; off; off >>= 1) sum += __shfl_xor_sync(0xffffffffu, sum, off);
    __syncthreads();
    if ((tid & 31) == 0) sred[tid >> 5] = sum;
    __syncthreads();
    float tot = sred[0] + sred[1] + sred[2] + sred[3] + sred[4] + sred[5] + sred[6] + sred[7];
    float inv = 1.f / tot;
    #pragma unroll
    for (int t = 0; t < 10; t++) p[tid + t * 256] = rnd_tf32(vals[t] * inv);
}

// ---------------- pipelined tensor-core TF32 NT GEMM ----------------
// C = A(MxK) * B(NxK)^T. Operands are fed RAW to mma.sync: tf32 occupies the
// top 19 bits of the fp32 layout, so the MMA unit truncates in HW (CUTLASS
// fast path). Activations are pre-rounded by producers; weights truncate.
// EPI 0: tf32-rounded store ; EPI 1: bias + tanh-GELU (rounded) ;
// EPI 2: res + gate[col]*(acc+bias), full fp32.
__device__ __forceinline__ float gelu_tanh(float x) {
    float x3 = x * x * x;
    return 0.5f * x * (1.f + tanhf(0.7978845608028654f * (x + 0.044715f * x3)));
}

__device__ __forceinline__ void mma_tf32(float c[4], const uint32_t a[4],
                                         uint32_t b0, uint32_t b1) {
    asm volatile(
        "mma.sync.aligned.m16n8k8.row.col.f32.tf32.tf32.f32 "
        "{%0,%1,%2,%3}, {%4,%5,%6,%7}, {%8,%9}, {%0,%1,%2,%3};\n"
        : "+f"(c[0]), "+f"(c[1]), "+f"(c[2]), "+f"(c[3])
        : "r"(a[0]), "r"(a[1]), "r"(a[2]), "r"(a[3]), "r"(b0), "r"(b1));
}

__device__ __forceinline__ void cp16(float* smem_dst, const float* gsrc) {
    uint32_t s = (uint32_t)__cvta_generic_to_shared(smem_dst);
    asm volatile("cp.async.cg.shared.global [%0], [%1], 16;\n" :: "r"(s), "l"(gsrc));
}

constexpr int STAGES = 4;
constexpr int PITCH  = 20;                       // words per row, conflict-free
constexpr int TILE_W = 128 * PITCH;              // words per (tile, stage)
constexpr size_t GEMM_SMEM = (size_t)STAGES * 2 * TILE_W * sizeof(float);  // 81920

// CTA tile 128x128, BK=16, 4 warps (2M x 2N), warp tile 64x64, 128 threads.
template <int EPI>
__global__ __launch_bounds__(128, 2) void gemm_tc(
    const float* __restrict__ A, size_t sA,
    const float* __restrict__ B, size_t sB,
    float* __restrict__ C, size_t sC, int ldc,
    const float* __restrict__ bias,
    const float* __restrict__ gate,
    const float* __restrict__ res,
    int M, int N, int K)
{
    A += (size_t)blockIdx.z * sA;
    B += (size_t)blockIdx.z * sB;
    C += (size_t)blockIdx.z * sC;
    extern __shared__ float smem[];
    float* As = smem;                       // [STAGES][128][PITCH]
    float* Bs = smem + STAGES * TILE_W;

    int tid  = threadIdx.x;
    int warp = tid >> 5, lane = tid & 31;
    int wm = warp >> 1, wn = warp & 1;      // 2 x 2 warp grid, 64x64 tiles
    int qd = lane >> 2, s = lane & 3;       // quad row / quad lane
    const float* Ag = A + (size_t)(blockIdx.y * 128) * K;
    const float* Bg = B + (size_t)(blockIdx.x * 128) * K;

    // fill mapping: i in 0..3, row = i*32 + (tid>>2), c4 = (tid&3)*4.
    int frow = tid >> 2;
    int fc4  = (tid & 3) * 4;

    float acc[4][8][4] = {};
    int nk = K >> 4;

    auto prefetch = [&](int k0i, int st) {
        int kbase = k0i * 16 + fc4;
        float* as = As + st * TILE_W;
        float* bs = Bs + st * TILE_W;
        #pragma unroll
        for (int i = 0; i < 4; i++) {
            int row = i * 32 + frow;
            cp16(as + row * PITCH + fc4, Ag + (size_t)row * K + kbase);
            cp16(bs + row * PITCH + fc4, Bg + (size_t)row * K + kbase);
        }
    };

    // prologue: fill STAGES-1 stages
    #pragma unroll
    for (int st = 0; st < STAGES - 1; st++) {
        if (st < nk) prefetch(st, st);
        asm volatile("cp.async.commit_group;\n");
    }

    for (int k0i = 0; k0i < nk; k0i++) {
        asm volatile("cp.async.wait_group %0;\n" :: "n"(STAGES - 2));
        __syncthreads();

        const float* as = As + (k0i % STAGES) * TILE_W;
        const float* bs = Bs + (k0i % STAGES) * TILE_W;
        #pragma unroll
        for (int kk = 0; kk < 16; kk += 8) {
            uint32_t afr[4][4];
            #pragma unroll
            for (int tm = 0; tm < 4; tm++) {
                int r = wm * 64 + tm * 16 + qd;
                afr[tm][0] = __float_as_uint(as[r * PITCH + kk + s]);
                afr[tm][1] = __float_as_uint(as[(r + 8) * PITCH + kk + s]);
                afr[tm][2] = __float_as_uint(as[r * PITCH + kk + 4 + s]);
                afr[tm][3] = __float_as_uint(as[(r + 8) * PITCH + kk + 4 + s]);
            }
            #pragma unroll
            for (int tn = 0; tn < 8; tn++) {
                int col = wn * 64 + tn * 8 + qd;
                uint32_t b0 = __float_as_uint(bs[col * PITCH + kk + s]);
                uint32_t b1 = __float_as_uint(bs[col * PITCH + kk + 4 + s]);
                #pragma unroll
                for (int tm = 0; tm < 4; tm++)
                    mma_tf32(acc[tm][tn], afr[tm], b0, b1);
            }
        }

        int pf = k0i + STAGES - 1;
        if (pf < nk) prefetch(pf, pf % STAGES);
        asm volatile("cp.async.commit_group;\n");
    }

    // epilogue: c0=C[q][2s], c1=C[q][2s+1], c2=C[q+8][2s], c3=C[q+8][2s+1]
    int row_base = blockIdx.y * 128 + wm * 64 + qd;
    int col_base = blockIdx.x * 128 + wn * 64;
    #pragma unroll
    for (int tm = 0; tm < 4; tm++) {
        #pragma unroll
        for (int tn = 0; tn < 8; tn++) {
            int col = col_base + tn * 8 + 2 * s;
            #pragma unroll
            for (int half = 0; half < 2; half++) {
                int row = row_base + tm * 16 + half * 8;
                float v0 = acc[tm][tn][half * 2 + 0];
                float v1 = acc[tm][tn][half * 2 + 1];
                if (EPI == 0) {
                    v0 = rnd_tf32(v0);
                    v1 = rnd_tf32(v1);
                } else if (EPI == 1) {
                    v0 = rnd_tf32(gelu_tanh(v0 + bias[col]));
                    v1 = rnd_tf32(gelu_tanh(v1 + bias[col + 1]));
                } else if (EPI == 2) {
                    if (bias) { v0 += bias[col]; v1 += bias[col + 1]; }
                    const float* rp = res + (size_t)row * ldc + col;
                    v0 = rp[0] + gate[col] * v0;
                    v1 = rp[1] + gate[col + 1] * v1;
                }
                *(float2*)&C[(size_t)row * ldc + col] = make_float2(v0, v1);
            }
        }
    }
}

// ---------------- launch ----------------
extern "C" void kernel_launch(void* const* d_in, const int* in_sizes, int n_in,
                              void* d_out, int out_size) {
    const float* txt           = (const float*)d_in[0];
    const float* img           = (const float*)d_in[1];
    const float* vec           = (const float*)d_in[2];
    const float* rope          = (const float*)d_in[3];
    const float* txt_adaln_w   = (const float*)d_in[4];
    const float* txt_adaln_b   = (const float*)d_in[5];
    const float* txt_adaln_rms = (const float*)d_in[6];
    const float* img_adaln_w   = (const float*)d_in[7];
    const float* img_adaln_b   = (const float*)d_in[8];
    const float* img_adaln_rms = (const float*)d_in[9];
    const float* txt_qkv_w     = (const float*)d_in[10];
    const float* img_qkv_w     = (const float*)d_in[11];
    const float* txt_out_w     = (const float*)d_in[12];
    const float* img_out_w     = (const float*)d_in[13];
    const float* txt_norm2_w   = (const float*)d_in[14];
    const float* img_norm2_w   = (const float*)d_in[15];
    const float* txt_fc1_w     = (const float*)d_in[16];
    const float* txt_fc1_b     = (const float*)d_in[17];
    const float* txt_fc2_w     = (const float*)d_in[18];
    const float* txt_fc2_b     = (const float*)d_in[19];
    const float* img_fc1_w     = (const float*)d_in[20];
    const float* img_fc1_b     = (const float*)d_in[21];
    const float* img_fc2_w     = (const float*)d_in[22];
    const float* img_fc2_b     = (const float*)d_in[23];
    float* out = (float*)d_out;
    (void)in_sizes; (void)n_in; (void)out_size;

    static bool attr_done = false;
    if (!attr_done) {
        cudaFuncSetAttribute(gemm_tc<0>, cudaFuncAttributeMaxDynamicSharedMemorySize, (int)GEMM_SMEM);
        cudaFuncSetAttribute(gemm_tc<1>, cudaFuncAttributeMaxDynamicSharedMemorySize, (int)GEMM_SMEM);
        cudaFuncSetAttribute(gemm_tc<2>, cudaFuncAttributeMaxDynamicSharedMemorySize, (int)GEMM_SMEM);
        attr_done = true;
    }

    float* sc = nullptr;
    cudaGetSymbolAddress((void**)&sc, g_scratch);
    float* silu = sc + OFF_SILU;
    float* mod  = sc + OFF_MOD;
    float* tmod = mod;
    float* imod = mod + 6 * kH;
    float* xn   = sc + OFF_XN;
    float* qkv  = sc + OFF_QKV;
    float* q    = sc + OFF_Q;
    float* k    = sc + OFF_K;
    float* vt   = sc + OFF_VT;
    float* S    = sc + OFF_S;
    float* ao   = sc + OFF_AO;
    float* res  = sc + OFF_RES;
    float* h1   = sc + OFF_H1;

    // adaLN modulation params
    silu_kernel<<<8, 256>>>(vec, silu);
    adaln_gemv<<<(2 * 6 * kH) / 8, 256>>>(silu, txt_adaln_w, txt_adaln_b,
                                          img_adaln_w, img_adaln_b, mod);

    // norm1 + modulation
    norm_mod<<<kL, 256>>>(txt, xn, txt_adaln_rms, tmod, tmod + kH);
    norm_mod<<<kN, 256>>>(img, xn + (size_t)kL * kH, img_adaln_rms, imod, imod + kH);

    // QKV projections
    gemm_tc<0><<<dim3(3 * kH / 128, kL / 128), 128, GEMM_SMEM>>>(
        xn, 0, txt_qkv_w, 0, qkv, 0, 3 * kH, nullptr, nullptr, nullptr, kL, 3 * kH, kH);
    gemm_tc<0><<<dim3(3 * kH / 128, kN / 128), 128, GEMM_SMEM>>>(
        xn + (size_t)kL * kH, 0, img_qkv_w, 0, qkv + (size_t)kL * 3 * kH, 0, 3 * kH,
        nullptr, nullptr, nullptr, kN, 3 * kH, kH);

    // RoPE + head scatter (V transposed, Q pre-scaled)
    rope_scatter<<<(kSEQ * kHEADS * 64) / 256, 256>>>(qkv, rope, q, k, vt);

    // joint attention: S = Q K^T (per head), softmax, O = P V
    gemm_tc<0><<<dim3(kSEQ / 128, kSEQ / 128, kHEADS), 128, GEMM_SMEM>>>(
        q, (size_t)kSEQ * kHD, k, (size_t)kSEQ * kHD, S, (size_t)kSEQ * kSEQ, kSEQ,
        nullptr, nullptr, nullptr, kSEQ, kSEQ, kHD);
    softmax_rows<<<dim3(kSEQ, kHEADS), 256>>>(S);
    gemm_tc<0><<<dim3(kHD / 128, kSEQ / 128, kHEADS), 128, GEMM_SMEM>>>(
        S, (size_t)kSEQ * kSEQ, vt, (size_t)kHD * kSEQ, ao, (size_t)kHD, kH,
        nullptr, nullptr, nullptr, kSEQ, kHD, kSEQ);

    // output projections with gated residual
    gemm_tc<2><<<dim3(kH / 128, kL / 128), 128, GEMM_SMEM>>>(
        ao, 0, txt_out_w, 0, res, 0, kH, nullptr, tmod + 2 * kH, txt, kL, kH, kH);
    gemm_tc<2><<<dim3(kH / 128, kN / 128), 128, GEMM_SMEM>>>(
        ao + (size_t)kL * kH, 0, img_out_w, 0, res + (size_t)kL * kH, 0, kH,
        nullptr, imod + 2 * kH, img, kN, kH, kH);

    // norm2 + modulation
    norm_mod<<<kL, 256>>>(res, xn, txt_norm2_w, tmod + 3 * kH, tmod + 4 * kH);
    norm_mod<<<kN, 256>>>(res + (size_t)kL * kH, xn + (size_t)kL * kH,
                          img_norm2_w, imod + 3 * kH, imod + 4 * kH);

    // txt MLP
    gemm_tc<1><<<dim3(kMLP / 128, kL / 128), 128, GEMM_SMEM>>>(
        xn, 0, txt_fc1_w, 0, h1, 0, kMLP, txt_fc1_b, nullptr, nullptr, kL, kMLP, kH);
    gemm_tc<2><<<dim3(kH / 128, kL / 128), 128, GEMM_SMEM>>>(
        h1, 0, txt_fc2_w, 0, out, 0, kH, txt_fc2_b, tmod + 5 * kH, res, kL, kH, kMLP);

    // img MLP
    gemm_tc<1><<<dim3(kMLP / 128, kN / 128), 128, GEMM_SMEM>>>(
        xn + (size_t)kL * kH, 0, img_fc1_w, 0, h1, 0, kMLP, img_fc1_b, nullptr, nullptr,
        kN, kMLP, kH);
    gemm_tc<2><<<dim3(kH / 128, kN / 128), 128, GEMM_SMEM>>>(
        h1, 0, img_fc2_w, 0, out + (size_t)kL * kH, 0, kH, img_fc2_b, imod + 5 * kH,
        res + (size_t)kL * kH, kN, kH, kMLP);
}

// round 7
// speedup vs baseline: 3.7448x; 1.1377x over previous
#include <cuda_runtime.h>
#include <math.h>
#include <stdint.h>

// ---------------- problem constants ----------------
constexpr int kH     = 2048;
constexpr int kL     = 512;    // txt tokens
constexpr int kN     = 2048;   // img tokens
constexpr int kSEQ   = 2560;   // joint sequence
constexpr int kHEADS = 16;
constexpr int kHD    = 128;
constexpr int kMLP   = 8192;

// ---------------- scratch layout (single __device__ array, no allocs) ----
constexpr size_t OFF_SILU = 0;
constexpr size_t OFF_MOD  = OFF_SILU + kH;
constexpr size_t OFF_XN   = OFF_MOD  + (size_t)2 * 6 * kH;
constexpr size_t OFF_QKV  = OFF_XN   + (size_t)kSEQ * kH;
constexpr size_t OFF_Q    = OFF_QKV  + (size_t)kSEQ * 3 * kH;
constexpr size_t OFF_K    = OFF_Q    + (size_t)kHEADS * kSEQ * kHD;
constexpr size_t OFF_VT   = OFF_K    + (size_t)kHEADS * kSEQ * kHD;
constexpr size_t OFF_S    = OFF_VT   + (size_t)kHEADS * kHD * kSEQ;
constexpr size_t OFF_AO   = OFF_S    + (size_t)kHEADS * kSEQ * kSEQ;
constexpr size_t OFF_AOP  = OFF_AO   + (size_t)kSEQ * kH;            // 4 partials
constexpr size_t OFF_RES  = OFF_AOP  + (size_t)4 * kSEQ * kH;
constexpr size_t OFF_H1   = OFF_RES  + (size_t)kSEQ * kH;            // img h1
constexpr size_t OFF_H1T  = OFF_H1   + (size_t)kN * kMLP;            // txt h1
constexpr size_t SCRATCH_TOTAL = OFF_H1T + (size_t)kL * kMLP;

__device__ __align__(256) float g_scratch[SCRATCH_TOTAL];

// round fp32 -> tf32 (rna), result kept in fp32 container
__device__ __forceinline__ float rnd_tf32(float x) {
    uint32_t y;
    asm("cvt.rna.tf32.f32 %0, %1;" : "=r"(y) : "f"(x));
    return __uint_as_float(y);
}

// ---------------- small helper kernels ----------------
__global__ void silu_kernel(const float* __restrict__ vec, float* __restrict__ out) {
    int i = blockIdx.x * blockDim.x + threadIdx.x;
    if (i < kH) {
        float v = vec[i];
        out[i] = v / (1.f + expf(-v));
    }
}

__global__ void adaln_gemv(const float* __restrict__ silu,
                           const float* __restrict__ tw, const float* __restrict__ tb,
                           const float* __restrict__ iw, const float* __restrict__ ib,
                           float* __restrict__ mod) {
    int gw = (blockIdx.x * blockDim.x + threadIdx.x) >> 5;
    int lane = threadIdx.x & 31;
    if (gw >= 2 * 6 * kH) return;
    int set = gw / (6 * kH);
    int o = gw - set * (6 * kH);
    const float* W = (set ? iw : tw) + (size_t)o * kH;
    float s = 0.f;
    for (int i = lane; i < kH; i += 32) s += silu[i] * W[i];
    #pragma unroll
    for (int off = 16; off; off >>= 1) s += __shfl_xor_sync(0xffffffffu, s, off);
    if (lane == 0) mod[(size_t)set * 6 * kH + o] = s + (set ? ib[o] : tb[o]);
}

// out = tf32_round(rms_norm(x, w) * (1 + sc) + sh)
__global__ void norm_mod(const float* __restrict__ x, float* __restrict__ out,
                         const float* __restrict__ w,
                         const float* __restrict__ sh, const float* __restrict__ sc) {
    int row = blockIdx.x;
    const float* xr = x + (size_t)row * kH;
    float* orow = out + (size_t)row * kH;
    int tid = threadIdx.x;
    float ss = 0.f;
    for (int i = tid; i < kH; i += 256) { float v = xr[i]; ss += v * v; }
    __shared__ float sred[8];
    #pragma unroll
    for (int off = 16; off; off >>= 1) ss += __shfl_xor_sync(0xffffffffu, ss, off);
    if ((tid & 31) == 0) sred[tid >> 5] = ss;
    __syncthreads();
    if (tid < 8) {
        float v = sred[tid];
        #pragma unroll
        for (int off = 4; off; off >>= 1) v += __shfl_xor_sync(0xffu, v, off);
        if (tid == 0) sred[0] = v;
    }
    __syncthreads();
    float norm = rsqrtf(sred[0] * (1.f / kH) + 1e-6f);
    for (int i = tid; i < kH; i += 256)
        orow[i] = rnd_tf32(xr[i] * norm * w[i] * (1.f + sc[i]) + sh[i]);
}

// Split qkv, apply RoPE to img q/k, scatter heads; v stored transposed.
__global__ void rope_scatter(const float* __restrict__ qkv, const float* __restrict__ rope,
                             float* __restrict__ q, float* __restrict__ k,
                             float* __restrict__ vt) {
    int gid = blockIdx.x * blockDim.x + threadIdx.x;
    if (gid >= kSEQ * kHEADS * (kHD / 2)) return;
    int j = gid & 63;
    int h = (gid >> 6) & 15;
    int n = gid >> 10;
    int d = j * 2;
    const float qscale = 0.08838834764831845f;
    const float* base = qkv + (size_t)n * 3 * kH;
    float q0 = base[h * kHD + d],          q1 = base[h * kHD + d + 1];
    float k0 = base[kH + h * kHD + d],     k1 = base[kH + h * kHD + d + 1];
    float v0 = base[2 * kH + h * kHD + d], v1 = base[2 * kH + h * kHD + d + 1];
    if (n >= kL) {
        const float* r = rope + (size_t)(n - kL) * kHD + d;
        float c = r[0], s = r[1];
        float t;
        t = q0 * c - q1 * s; q1 = q1 * c + q0 * s; q0 = t;
        t = k0 * c - k1 * s; k1 = k1 * c + k0 * s; k0 = t;
    }
    size_t qi = ((size_t)h * kSEQ + n) * kHD + d;
    q[qi] = rnd_tf32(q0 * qscale); q[qi + 1] = rnd_tf32(q1 * qscale);
    k[qi] = rnd_tf32(k0); k[qi + 1] = rnd_tf32(k1);
    size_t vi = ((size_t)h * kHD + d) * kSEQ + n;
    vt[vi] = rnd_tf32(v0); vt[vi + kSEQ] = rnd_tf32(v1);
}

// Row softmax over 2560 (Q pre-scaled); output tf32-rounded (feeds PV GEMM).
__global__ void softmax_rows(float* __restrict__ S) {
    float* p = S + ((size_t)blockIdx.y * kSEQ + blockIdx.x) * kSEQ;
    int tid = threadIdx.x;
    float vals[10];
    float m = -3.4e38f;
    #pragma unroll
    for (int t = 0; t < 10; t++) { vals[t] = p[tid + t * 256]; m = fmaxf(m, vals[t]); }
    __shared__ float sred[8];
    #pragma unroll
    for (int off = 16; off; off >>= 1) m = fmaxf(m, __shfl_xor_sync(0xffffffffu, m, off));
    if ((tid & 31) == 0) sred[tid >> 5] = m;
    __syncthreads();
    float m2 = sred[0];
    #pragma unroll
    for (int i = 1; i < 8; i++) m2 = fmaxf(m2, sred[i]);
    float sum = 0.f;
    #pragma unroll
    for (int t = 0; t < 10; t++) { vals[t] = __expf(vals[t] - m2); sum += vals[t]; }
    #pragma unroll
    for (int off = 16; off; off >>= 1) sum += __shfl_xor_sync(0xffffffffu, sum, off);
    __syncthreads();
    if ((tid & 31) == 0) sred[tid >> 5] = sum;
    __syncthreads();
    float tot = sred[0] + sred[1] + sred[2] + sred[3] + sred[4] + sred[5] + sred[6] + sred[7];
    float inv = 1.f / tot;
    #pragma unroll
    for (int t = 0; t < 10; t++) p[tid + t * 256] = rnd_tf32(vals[t] * inv);
}

// ao = rnd_tf32(p0 + p1 + p2 + p3)
__global__ void add_pv(const float4* __restrict__ p, float4* __restrict__ ao) {
    const size_t n = (size_t)kSEQ * kH / 4;
    size_t i = (size_t)blockIdx.x * blockDim.x + threadIdx.x;
    if (i >= n) return;
    float4 a = p[i], b = p[i + n], c = p[i + 2 * n], d = p[i + 3 * n];
    float4 o;
    o.x = rnd_tf32(a.x + b.x + c.x + d.x);
    o.y = rnd_tf32(a.y + b.y + c.y + d.y);
    o.z = rnd_tf32(a.z + b.z + c.z + d.z);
    o.w = rnd_tf32(a.w + b.w + c.w + d.w);
    ao[i] = o;
}

// ---------------- pipelined tensor-core TF32 NT GEMM ----------------
// C = A(MxK) * B(NxK)^T, raw fp32 bits into mma.sync (HW tf32 truncation).
// EPI 0: tf32-rounded store ; EPI 1: bias + tanh-GELU (rounded) ;
// EPI 2: res + gate[col]*(acc+bias), full fp32.
// SPLIT=1: PV split-K mode (y = qblock*4 + kslice, z = head), raw fp32 store.
__device__ __forceinline__ float gelu_tanh(float x) {
    float x3 = x * x * x;
    return 0.5f * x * (1.f + tanhf(0.7978845608028654f * (x + 0.044715f * x3)));
}

__device__ __forceinline__ void mma_tf32(float c[4], const uint32_t a[4],
                                         uint32_t b0, uint32_t b1) {
    asm volatile(
        "mma.sync.aligned.m16n8k8.row.col.f32.tf32.tf32.f32 "
        "{%0,%1,%2,%3}, {%4,%5,%6,%7}, {%8,%9}, {%0,%1,%2,%3};\n"
        : "+f"(c[0]), "+f"(c[1]), "+f"(c[2]), "+f"(c[3])
        : "r"(a[0]), "r"(a[1]), "r"(a[2]), "r"(a[3]), "r"(b0), "r"(b1));
}

__device__ __forceinline__ void cp16(float* smem_dst, const float* gsrc) {
    uint32_t s = (uint32_t)__cvta_generic_to_shared(smem_dst);
    asm volatile("cp.async.cg.shared.global [%0], [%1], 16;\n" :: "r"(s), "l"(gsrc));
}

constexpr int STAGES = 4;
constexpr int PITCH  = 20;
constexpr int TILE_W = 128 * PITCH;
constexpr size_t GEMM_SMEM = (size_t)STAGES * 2 * TILE_W * sizeof(float);  // 81920
constexpr int PV_KSLC = 640;                     // K per PV slice
constexpr size_t PV_PART = (size_t)kSEQ * kH;    // partial buffer stride

template <int EPI, int SPLIT>
__global__ __launch_bounds__(128, 2) void gemm_tc(
    const float* __restrict__ A, size_t sA,
    const float* __restrict__ B, size_t sB,
    float* __restrict__ C, size_t sC, int ldc,
    int lda, int ldb,
    const float* __restrict__ bias,
    const float* __restrict__ gate,
    const float* __restrict__ res,
    int M, int N, int K)
{
    const float* Ag;
    const float* Bg;
    int yb;
    if (SPLIT) {
        int head = blockIdx.z, qb = blockIdx.y >> 2, ks = blockIdx.y & 3;
        yb = qb * 128;
        Ag = A + (size_t)head * sA + (size_t)ks * PV_KSLC + (size_t)yb * lda;
        Bg = B + (size_t)head * sB + (size_t)ks * PV_KSLC
               + (size_t)(blockIdx.x * 128) * ldb;
        C += (size_t)ks * PV_PART + (size_t)head * 128;
    } else {
        yb = blockIdx.y * 128;
        Ag = A + (size_t)blockIdx.z * sA + (size_t)yb * lda;
        Bg = B + (size_t)blockIdx.z * sB + (size_t)(blockIdx.x * 128) * ldb;
        C += (size_t)blockIdx.z * sC;
    }
    extern __shared__ float smem[];
    float* As = smem;                       // [STAGES][128][PITCH]
    float* Bs = smem + STAGES * TILE_W;

    int tid  = threadIdx.x;
    int warp = tid >> 5, lane = tid & 31;
    int wm = warp >> 1, wn = warp & 1;      // 2 x 2 warp grid, 64x64 tiles
    int qd = lane >> 2, s = lane & 3;

    int frow = tid >> 2;
    int fc4  = (tid & 3) * 4;

    float acc[4][8][4] = {};
    int nk = K >> 4;

    auto prefetch = [&](int k0i, int st) {
        int kbase = k0i * 16 + fc4;
        float* as = As + st * TILE_W;
        float* bs = Bs + st * TILE_W;
        #pragma unroll
        for (int i = 0; i < 4; i++) {
            int row = i * 32 + frow;
            cp16(as + row * PITCH + fc4, Ag + (size_t)row * lda + kbase);
            cp16(bs + row * PITCH + fc4, Bg + (size_t)row * ldb + kbase);
        }
    };

    #pragma unroll
    for (int st = 0; st < STAGES - 1; st++) {
        if (st < nk) prefetch(st, st);
        asm volatile("cp.async.commit_group;\n");
    }

    for (int k0i = 0; k0i < nk; k0i++) {
        asm volatile("cp.async.wait_group %0;\n" :: "n"(STAGES - 2));
        __syncthreads();

        const float* as = As + (k0i % STAGES) * TILE_W;
        const float* bs = Bs + (k0i % STAGES) * TILE_W;
        #pragma unroll
        for (int kk = 0; kk < 16; kk += 8) {
            uint32_t afr[4][4];
            #pragma unroll
            for (int tm = 0; tm < 4; tm++) {
                int r = wm * 64 + tm * 16 + qd;
                afr[tm][0] = __float_as_uint(as[r * PITCH + kk + s]);
                afr[tm][1] = __float_as_uint(as[(r + 8) * PITCH + kk + s]);
                afr[tm][2] = __float_as_uint(as[r * PITCH + kk + 4 + s]);
                afr[tm][3] = __float_as_uint(as[(r + 8) * PITCH + kk + 4 + s]);
            }
            #pragma unroll
            for (int tn = 0; tn < 8; tn++) {
                int col = wn * 64 + tn * 8 + qd;
                uint32_t b0 = __float_as_uint(bs[col * PITCH + kk + s]);
                uint32_t b1 = __float_as_uint(bs[col * PITCH + kk + 4 + s]);
                #pragma unroll
                for (int tm = 0; tm < 4; tm++)
                    mma_tf32(acc[tm][tn], afr[tm], b0, b1);
            }
        }

        int pf = k0i + STAGES - 1;
        if (pf < nk) prefetch(pf, pf % STAGES);
        asm volatile("cp.async.commit_group;\n");
    }

    int row_base = yb + wm * 64 + qd;
    int col_base = blockIdx.x * 128 + wn * 64;
    #pragma unroll
    for (int tm = 0; tm < 4; tm++) {
        #pragma unroll
        for (int tn = 0; tn < 8; tn++) {
            int col = col_base + tn * 8 + 2 * s;
            #pragma unroll
            for (int half = 0; half < 2; half++) {
                int row = row_base + tm * 16 + half * 8;
                float v0 = acc[tm][tn][half * 2 + 0];
                float v1 = acc[tm][tn][half * 2 + 1];
                if (EPI == 0 && !SPLIT) {
                    v0 = rnd_tf32(v0);
                    v1 = rnd_tf32(v1);
                } else if (EPI == 1) {
                    v0 = rnd_tf32(gelu_tanh(v0 + bias[col]));
                    v1 = rnd_tf32(gelu_tanh(v1 + bias[col + 1]));
                } else if (EPI == 2) {
                    if (bias) { v0 += bias[col]; v1 += bias[col + 1]; }
                    const float* rp = res + (size_t)row * ldc + col;
                    v0 = rp[0] + gate[col] * v0;
                    v1 = rp[1] + gate[col + 1] * v1;
                }
                *(float2*)&C[(size_t)row * ldc + col] = make_float2(v0, v1);
            }
        }
    }
}

// ---------------- launch ----------------
extern "C" void kernel_launch(void* const* d_in, const int* in_sizes, int n_in,
                              void* d_out, int out_size) {
    const float* txt           = (const float*)d_in[0];
    const float* img           = (const float*)d_in[1];
    const float* vec           = (const float*)d_in[2];
    const float* rope          = (const float*)d_in[3];
    const float* txt_adaln_w   = (const float*)d_in[4];
    const float* txt_adaln_b   = (const float*)d_in[5];
    const float* txt_adaln_rms = (const float*)d_in[6];
    const float* img_adaln_w   = (const float*)d_in[7];
    const float* img_adaln_b   = (const float*)d_in[8];
    const float* img_adaln_rms = (const float*)d_in[9];
    const float* txt_qkv_w     = (const float*)d_in[10];
    const float* img_qkv_w     = (const float*)d_in[11];
    const float* txt_out_w     = (const float*)d_in[12];
    const float* img_out_w     = (const float*)d_in[13];
    const float* txt_norm2_w   = (const float*)d_in[14];
    const float* img_norm2_w   = (const float*)d_in[15];
    const float* txt_fc1_w     = (const float*)d_in[16];
    const float* txt_fc1_b     = (const float*)d_in[17];
    const float* txt_fc2_w     = (const float*)d_in[18];
    const float* txt_fc2_b     = (const float*)d_in[19];
    const float* img_fc1_w     = (const float*)d_in[20];
    const float* img_fc1_b     = (const float*)d_in[21];
    const float* img_fc2_w     = (const float*)d_in[22];
    const float* img_fc2_b     = (const float*)d_in[23];
    float* out = (float*)d_out;
    (void)in_sizes; (void)n_in; (void)out_size;

    static cudaStream_t s1 = nullptr;
    static cudaEvent_t ev0 = nullptr, ev1 = nullptr, ev2 = nullptr, ev3 = nullptr;
    static bool attr_done = false;
    if (!attr_done) {
        cudaFuncSetAttribute((const void*)gemm_tc<0,0>, cudaFuncAttributeMaxDynamicSharedMemorySize, (int)GEMM_SMEM);
        cudaFuncSetAttribute((const void*)gemm_tc<1,0>, cudaFuncAttributeMaxDynamicSharedMemorySize, (int)GEMM_SMEM);
        cudaFuncSetAttribute((const void*)gemm_tc<2,0>, cudaFuncAttributeMaxDynamicSharedMemorySize, (int)GEMM_SMEM);
        cudaFuncSetAttribute((const void*)gemm_tc<0,1>, cudaFuncAttributeMaxDynamicSharedMemorySize, (int)GEMM_SMEM);
        cudaStreamCreateWithFlags(&s1, cudaStreamNonBlocking);
        cudaEventCreateWithFlags(&ev0, cudaEventDisableTiming);
        cudaEventCreateWithFlags(&ev1, cudaEventDisableTiming);
        cudaEventCreateWithFlags(&ev2, cudaEventDisableTiming);
        cudaEventCreateWithFlags(&ev3, cudaEventDisableTiming);
        attr_done = true;
    }

    float* sc = nullptr;
    cudaGetSymbolAddress((void**)&sc, g_scratch);
    float* silu = sc + OFF_SILU;
    float* mod  = sc + OFF_MOD;
    float* tmod = mod;
    float* imod = mod + 6 * kH;
    float* xn   = sc + OFF_XN;
    float* qkv  = sc + OFF_QKV;
    float* q    = sc + OFF_Q;
    float* k    = sc + OFF_K;
    float* vt   = sc + OFF_VT;
    float* S    = sc + OFF_S;
    float* ao   = sc + OFF_AO;
    float* aop  = sc + OFF_AOP;
    float* res  = sc + OFF_RES;
    float* h1   = sc + OFF_H1;
    float* h1t  = sc + OFF_H1T;

    // adaLN modulation params (main stream)
    silu_kernel<<<8, 256>>>(vec, silu);
    adaln_gemv<<<(2 * 6 * kH) / 8, 256>>>(silu, txt_adaln_w, txt_adaln_b,
                                          img_adaln_w, img_adaln_b, mod);

    // ---- fork: txt qkv chain on s1, img qkv chain on main ----
    cudaEventRecord(ev0, 0);
    cudaStreamWaitEvent(s1, ev0, 0);

    norm_mod<<<kL, 256, 0, s1>>>(txt, xn, txt_adaln_rms, tmod, tmod + kH);
    gemm_tc<0,0><<<dim3(3 * kH / 128, kL / 128), 128, GEMM_SMEM, s1>>>(
        xn, 0, txt_qkv_w, 0, qkv, 0, 3 * kH, kH, kH,
        nullptr, nullptr, nullptr, kL, 3 * kH, kH);
    cudaEventRecord(ev1, s1);

    norm_mod<<<kN, 256>>>(img, xn + (size_t)kL * kH, img_adaln_rms, imod, imod + kH);
    gemm_tc<0,0><<<dim3(3 * kH / 128, kN / 128), 128, GEMM_SMEM>>>(
        xn + (size_t)kL * kH, 0, img_qkv_w, 0, qkv + (size_t)kL * 3 * kH, 0, 3 * kH,
        kH, kH, nullptr, nullptr, nullptr, kN, 3 * kH, kH);
    cudaStreamWaitEvent(0, ev1, 0);

    // RoPE + head scatter
    rope_scatter<<<(kSEQ * kHEADS * 64) / 256, 256>>>(qkv, rope, q, k, vt);

    // joint attention: S = Q K^T, softmax, O = P V (split-K=4)
    gemm_tc<0,0><<<dim3(kSEQ / 128, kSEQ / 128, kHEADS), 128, GEMM_SMEM>>>(
        q, (size_t)kSEQ * kHD, k, (size_t)kSEQ * kHD, S, (size_t)kSEQ * kSEQ, kSEQ,
        kHD, kHD, nullptr, nullptr, nullptr, kSEQ, kSEQ, kHD);
    softmax_rows<<<dim3(kSEQ, kHEADS), 256>>>(S);
    gemm_tc<0,1><<<dim3(1, (kSEQ / 128) * 4, kHEADS), 128, GEMM_SMEM>>>(
        S, (size_t)kSEQ * kSEQ, vt, (size_t)kHD * kSEQ, aop, 0, kH,
        kSEQ, kSEQ, nullptr, nullptr, nullptr, kSEQ, kHD, PV_KSLC);
    add_pv<<<(kSEQ * kH / 4 + 255) / 256, 256>>>((const float4*)aop, (float4*)ao);

    // ---- fork: txt tail on s1, img tail on main ----
    cudaEventRecord(ev2, 0);
    cudaStreamWaitEvent(s1, ev2, 0);

    // txt: out-proj, norm2, fc1, fc2
    gemm_tc<2,0><<<dim3(kH / 128, kL / 128), 128, GEMM_SMEM, s1>>>(
        ao, 0, txt_out_w, 0, res, 0, kH, kH, kH,
        nullptr, tmod + 2 * kH, txt, kL, kH, kH);
    norm_mod<<<kL, 256, 0, s1>>>(res, xn, txt_norm2_w, tmod + 3 * kH, tmod + 4 * kH);
    gemm_tc<1,0><<<dim3(kMLP / 128, kL / 128), 128, GEMM_SMEM, s1>>>(
        xn, 0, txt_fc1_w, 0, h1t, 0, kMLP, kH, kH,
        txt_fc1_b, nullptr, nullptr, kL, kMLP, kH);
    gemm_tc<2,0><<<dim3(kH / 128, kL / 128), 128, GEMM_SMEM, s1>>>(
        h1t, 0, txt_fc2_w, 0, out, 0, kH, kMLP, kMLP,
        txt_fc2_b, tmod + 5 * kH, res, kL, kH, kMLP);
    cudaEventRecord(ev3, s1);

    // img: out-proj, norm2, fc1, fc2
    gemm_tc<2,0><<<dim3(kH / 128, kN / 128), 128, GEMM_SMEM>>>(
        ao + (size_t)kL * kH, 0, img_out_w, 0, res + (size_t)kL * kH, 0, kH, kH, kH,
        nullptr, imod + 2 * kH, img, kN, kH, kH);
    norm_mod<<<kN, 256>>>(res + (size_t)kL * kH, xn + (size_t)kL * kH,
                          img_norm2_w, imod + 3 * kH, imod + 4 * kH);
    gemm_tc<1,0><<<dim3(kMLP / 128, kN / 128), 128, GEMM_SMEM>>>(
        xn + (size_t)kL * kH, 0, img_fc1_w, 0, h1, 0, kMLP, kH, kH,
        img_fc1_b, nullptr, nullptr, kN, kMLP, kH);
    gemm_tc<2,0><<<dim3(kH / 128, kN / 128), 128, GEMM_SMEM>>>(
        h1, 0, img_fc2_w, 0, out + (size_t)kL * kH, 0, kH, kMLP, kMLP,
        img_fc2_b, imod + 5 * kH, res + (size_t)kL * kH, kN, kH, kMLP);

    cudaStreamWaitEvent(0, ev3, 0);
}